// round 4
// baseline (speedup 1.0000x reference)
#include <cuda_runtime.h>

// Shapes (fixed): B=8, H=12, D=64, S=1024
// scores[b,h,s,t] = (1/8) * sum_d K[b,h,d,s] * Q[b,h,d,t]
// mask over t (per b), softmax over t (per (bh,s) row),
// context[b,h,d,t] = sum_s V[b,h,d,s]*attn[b,h,s,t]
// out = concat( context as (B,S,H*D), attn as (B,H,S,S) )
//
// Pipeline:
//  qk_kernel : QK GEMM (FFMA2, cp.async both d-chunks) -> E=exp(score/8)*mask
//              into g_E scratch + per-(s, t-block) partial row sums (g_part).
//  pv_kernel : block-specialized. GEMM blocks: ctx partial = E^T x (inv*V)
//              (inv folded into V operand, E double-buffered via cp.async).
//              Norm blocks: attn = E * inv (pure bandwidth), interleaved 4:1.
//  reduce    : sum 4 ctx partials.

#define D_DIM 64
#define S_DIM 1024
#define H_NUM 12
#define B_NUM 8
#define NBH   (B_NUM * H_NUM)
#define CTX_ELEMS ((size_t)B_NUM * S_DIM * H_NUM * D_DIM)   // 6291456

typedef unsigned long long ull;

__device__ __forceinline__ ull pack_dup(float x) {
    ull r; asm("mov.b64 %0, {%1,%2};" : "=l"(r) : "f"(x), "f"(x)); return r;
}
__device__ __forceinline__ void unpack2(ull v, float& lo, float& hi) {
    asm("mov.b64 {%0,%1}, %2;" : "=f"(lo), "=f"(hi) : "l"(v));
}
__device__ __forceinline__ ull fma2(ull a, ull b, ull c) {
    ull d; asm("fma.rn.f32x2 %0, %1, %2, %3;" : "=l"(d) : "l"(a), "l"(b), "l"(c));
    return d;
}
__device__ __forceinline__ unsigned s2u(const void* p) {
    return (unsigned)__cvta_generic_to_shared(p);
}
#define CP16(dst, src) asm volatile("cp.async.cg.shared.global [%0], [%1], 16;" :: "r"(s2u(dst)), "l"(src))
#define CP_COMMIT()    asm volatile("cp.async.commit_group;")
#define CP_WAIT(n)     asm volatile("cp.async.wait_group %0;" :: "n"(n))

// E scratch: [bh][s][t]  (unnormalized exp)
__device__ float g_E[(size_t)NBH * S_DIM * S_DIM];
// Partial row sums from qk: [t_block(8)][bh(96)][s(1024)]
__device__ float g_part[8 * NBH * S_DIM];
// Partial context from pv s-splits: [s_chunk(4)][ctx layout]
__device__ float g_ctxp[4 * CTX_ELEMS];

// ---------------------------------------------------------------------------
// Kernel 1: QK^T GEMM + exp + mask. Tile 128(s) x 128(t), K = 64 (d, 2 chunks
// of 32 prefetched via cp.async). Micro: 16(s, f32x2 pairs) x 4(t).
// ---------------------------------------------------------------------------
__global__ __launch_bounds__(256, 2) void qk_kernel(
    const float* __restrict__ Q, const float* __restrict__ K,
    const int* __restrict__ mask)
{
    extern __shared__ float smq[];
    float (*As)[32][128] = (float(*)[32][128])smq;            // [2][32][128]
    float (*Bs)[32][128] = (float(*)[32][128])(smq + 8192);

    const int bh = blockIdx.z;
    const int s0 = blockIdx.y * 128;
    const int t0 = blockIdx.x * 128;
    const float* Kb = K + (size_t)bh * D_DIM * S_DIM;
    const float* Qb = Q + (size_t)bh * D_DIM * S_DIM;

    const int tid = threadIdx.x;
    const int tx = tid & 31;        // t micro: t0 + tx*4 + j
    const int ty = tid >> 5;        // s micro: s0 + ty*16 + r
    const int lrow = tid >> 5;
    const int lcol = (tid & 31) * 4;

    // prefetch both d-chunks
#pragma unroll
    for (int ch = 0; ch < 2; ch++) {
#pragma unroll
        for (int j = 0; j < 4; j++) {
            const int row = lrow + j * 8;
            CP16(&As[ch][row][lcol], &Kb[(size_t)(ch * 32 + row) * S_DIM + s0 + lcol]);
            CP16(&Bs[ch][row][lcol], &Qb[(size_t)(ch * 32 + row) * S_DIM + t0 + lcol]);
        }
        CP_COMMIT();
    }

    ull c[8][4];
#pragma unroll
    for (int i = 0; i < 8; i++)
#pragma unroll
        for (int j = 0; j < 4; j++) c[i][j] = 0ULL;

#pragma unroll
    for (int ch = 0; ch < 2; ch++) {
        if (ch == 0) { CP_WAIT(1); } else { CP_WAIT(0); }
        __syncthreads();
#pragma unroll
        for (int k = 0; k < 32; k++) {
            const ulonglong2 a01 = *(const ulonglong2*)&As[ch][k][ty * 16];
            const ulonglong2 a23 = *(const ulonglong2*)&As[ch][k][ty * 16 + 4];
            const ulonglong2 a45 = *(const ulonglong2*)&As[ch][k][ty * 16 + 8];
            const ulonglong2 a67 = *(const ulonglong2*)&As[ch][k][ty * 16 + 12];
            const float4 bv = *(const float4*)&Bs[ch][k][tx * 4];
            const ull bd0 = pack_dup(bv.x);
            const ull bd1 = pack_dup(bv.y);
            const ull bd2 = pack_dup(bv.z);
            const ull bd3 = pack_dup(bv.w);
            ull a[8] = {a01.x, a01.y, a23.x, a23.y, a45.x, a45.y, a67.x, a67.y};
#pragma unroll
            for (int i = 0; i < 8; i++) {
                c[i][0] = fma2(a[i], bd0, c[i][0]);
                c[i][1] = fma2(a[i], bd1, c[i][1]);
                c[i][2] = fma2(a[i], bd2, c[i][2]);
                c[i][3] = fma2(a[i], bd3, c[i][3]);
            }
        }
    }

    // Epilogue: scale, mask, exp, store E to scratch, partial row sums.
    const int b = bh / H_NUM;
    const int4 mv = *(const int4*)&mask[b * S_DIM + t0 + tx * 4];
    const float m0 = mv.x ? 1.f : 0.f;
    const float m1 = mv.y ? 1.f : 0.f;
    const float m2 = mv.z ? 1.f : 0.f;
    const float m3 = mv.w ? 1.f : 0.f;

    float rs[16];
    const size_t base = ((size_t)bh * S_DIM + (s0 + ty * 16)) * S_DIM + t0 + tx * 4;
#pragma unroll
    for (int i = 0; i < 8; i++) {
        float l0, h0, l1, h1, l2, h2, l3, h3;
        unpack2(c[i][0], l0, h0);
        unpack2(c[i][1], l1, h1);
        unpack2(c[i][2], l2, h2);
        unpack2(c[i][3], l3, h3);
        float4 e0 = make_float4(__expf(l0 * 0.125f) * m0, __expf(l1 * 0.125f) * m1,
                                __expf(l2 * 0.125f) * m2, __expf(l3 * 0.125f) * m3);
        float4 e1 = make_float4(__expf(h0 * 0.125f) * m0, __expf(h1 * 0.125f) * m1,
                                __expf(h2 * 0.125f) * m2, __expf(h3 * 0.125f) * m3);
        *(float4*)&g_E[base + (size_t)(2 * i) * S_DIM] = e0;
        *(float4*)&g_E[base + (size_t)(2 * i + 1) * S_DIM] = e1;
        rs[2 * i]     = (e0.x + e0.y) + (e0.z + e0.w);
        rs[2 * i + 1] = (e1.x + e1.y) + (e1.z + e1.w);
    }
#pragma unroll
    for (int r = 0; r < 16; r++) {
        float v = rs[r];
#pragma unroll
        for (int o = 16; o > 0; o >>= 1)
            v += __shfl_xor_sync(0xffffffffu, v, o);
        rs[r] = v;
    }
    if (tx == 0) {
        float* pp = &g_part[((blockIdx.x * NBH + bh) << 10) + s0 + ty * 16];
#pragma unroll
        for (int r4 = 0; r4 < 4; r4++)
            *(float4*)&pp[r4 * 4] =
                make_float4(rs[r4 * 4], rs[r4 * 4 + 1], rs[r4 * 4 + 2], rs[r4 * 4 + 3]);
    }
}

// ---------------------------------------------------------------------------
// Kernel 2: block-specialized PV GEMM + attn normalize.
// Grid = 15360 1D blocks of 128 threads, pattern of 5: bid%5==0 -> GEMM block
// (3072 total: 8 t-tiles x 4 s-chunks x 96 bh), else norm block (12288: each
// normalizes 8 attn rows).
// GEMM: tile 64(d) x 128(t) over a 256-s chunk; micro 16(d, pairs) x 4(t);
// E double-buffered via cp.async; inv[s] folded into the V operand.
// ---------------------------------------------------------------------------
__global__ __launch_bounds__(128, 4) void pv_kernel(
    const float* __restrict__ V, float* __restrict__ attn)
{
    extern __shared__ float smp[];
    float (*Es)[32][128] = (float(*)[32][128])smp;           // [2][32][128]
    float (*Vs)[32][68]  = (float(*)[32][68])(smp + 8192);   // [2][32][68]
    float* invs = smp + 8192 + 4352;                          // [256]

    const int bi = blockIdx.x;
    const int g  = bi / 5;
    const int r5 = bi - g * 5;
    const int tid = threadIdx.x;

    if (r5 != 0) {
        // ---- norm block: attn[rows] = g_E[rows] * inv ----
        const int n  = g * 4 + (r5 - 1);          // 0..12287
        const int bh = n >> 7;
        const int r0 = (n & 127) * 8;
        const float* Eb = g_E + (size_t)bh * S_DIM * S_DIM + (size_t)r0 * S_DIM;
        float* Ob = attn + (size_t)bh * S_DIM * S_DIM + (size_t)r0 * S_DIM;
        float* inv8 = smp;
        if (tid < 8) {
            float sum = 0.f;
#pragma unroll
            for (int tb = 0; tb < 8; tb++)
                sum += g_part[((tb * NBH + bh) << 10) + r0 + tid];
            inv8[tid] = 1.0f / sum;
        }
        __syncthreads();
        const int w = tid >> 5, lane = tid & 31;
#pragma unroll
        for (int rr = 0; rr < 2; rr++) {
            const int row = w * 2 + rr;
            const float iv = inv8[row];
#pragma unroll
            for (int p = 0; p < 8; p++) {
                const int idx = row * S_DIM + lane * 4 + p * 128;
                float4 e = *(const float4*)&Eb[idx];
                e.x *= iv; e.y *= iv; e.z *= iv; e.w *= iv;
                *(float4*)&Ob[idx] = e;
            }
        }
        return;
    }

    // ---- GEMM block ----
    const int t0   = (g & 7) * 128;
    const int scid = (g >> 3) & 3;
    const int bh   = g >> 5;
    const int sc0  = scid * 256;
    const int b = bh / H_NUM;
    const int h = bh - b * H_NUM;
    const float* Vb = V + (size_t)bh * D_DIM * S_DIM;
    const float* Eb = g_E + (size_t)bh * S_DIM * S_DIM;

    // 1/rowsum for this chunk's 256 s rows
#pragma unroll
    for (int j = 0; j < 2; j++) {
        const int s = tid + j * 128;
        float sum = 0.f;
#pragma unroll
        for (int tb = 0; tb < 8; tb++)
            sum += g_part[((tb * NBH + bh) << 10) + sc0 + s];
        invs[s] = 1.0f / sum;
    }
    __syncthreads();

    const int tx = tid & 31;          // t micro
    const int ty = tid >> 5;          // d micro: ty*16 ..
    const int vd = tid & 63;
    const int vhalf = tid >> 6;       // s half of the 32-chunk

    // E cp.async: 8 x 16B per thread per chunk
#define PV_CPE(ci, buf)                                                        \
    {                                                                          \
        _Pragma("unroll")                                                      \
        for (int u = 0; u < 8; u++) {                                          \
            const int id = tid + u * 128;                                      \
            const int row = id >> 5;                                           \
            const int c16 = (id & 31) * 4;                                     \
            CP16(&Es[buf][row][c16],                                           \
                 &Eb[(size_t)(sc0 + (ci) * 32 + row) * S_DIM + t0 + c16]);     \
        }                                                                      \
        CP_COMMIT();                                                           \
    }

    float4 vr[4];
#define PV_LDV(ci)                                                             \
    {                                                                          \
        const float* vp = &Vb[(size_t)vd * S_DIM + sc0 + (ci) * 32 + vhalf * 16];\
        vr[0] = *(const float4*)(vp + 0);                                      \
        vr[1] = *(const float4*)(vp + 4);                                      \
        vr[2] = *(const float4*)(vp + 8);                                      \
        vr[3] = *(const float4*)(vp + 12);                                     \
    }

#define PV_STV(ci, buf)                                                        \
    {                                                                          \
        _Pragma("unroll")                                                      \
        for (int q = 0; q < 4; q++) {                                          \
            const int sl = vhalf * 16 + q * 4;                                 \
            const float4 iv = *(const float4*)&invs[(ci) * 32 + sl];           \
            Vs[buf][sl + 0][vd] = vr[q].x * iv.x;                              \
            Vs[buf][sl + 1][vd] = vr[q].y * iv.y;                              \
            Vs[buf][sl + 2][vd] = vr[q].z * iv.z;                              \
            Vs[buf][sl + 3][vd] = vr[q].w * iv.w;                              \
        }                                                                      \
    }

    // prologue
    PV_CPE(0, 0);
    PV_LDV(0);
    CP_WAIT(0);
    PV_STV(0, 0);
    __syncthreads();

    ull c[4][8];   // [t j][d pair]
#pragma unroll
    for (int j = 0; j < 4; j++)
#pragma unroll
        for (int i = 0; i < 8; i++) c[j][i] = 0ULL;

    for (int ci = 0; ci < 8; ci++) {
        const int cur = ci & 1, nxt = cur ^ 1;
        if (ci < 7) { PV_CPE(ci + 1, nxt); PV_LDV(ci + 1); }
#pragma unroll
        for (int k = 0; k < 32; k++) {
            const ulonglong2 p0 = *(const ulonglong2*)&Vs[cur][k][ty * 16];
            const ulonglong2 p1 = *(const ulonglong2*)&Vs[cur][k][ty * 16 + 4];
            const ulonglong2 p2 = *(const ulonglong2*)&Vs[cur][k][ty * 16 + 8];
            const ulonglong2 p3 = *(const ulonglong2*)&Vs[cur][k][ty * 16 + 12];
            const float4 bv = *(const float4*)&Es[cur][k][tx * 4];
            const ull bd0 = pack_dup(bv.x);
            const ull bd1 = pack_dup(bv.y);
            const ull bd2 = pack_dup(bv.z);
            const ull bd3 = pack_dup(bv.w);
#pragma unroll
            for (int j = 0; j < 4; j++) {
                const ull bd = (j == 0) ? bd0 : (j == 1) ? bd1 : (j == 2) ? bd2 : bd3;
                c[j][0] = fma2(p0.x, bd, c[j][0]);
                c[j][1] = fma2(p0.y, bd, c[j][1]);
                c[j][2] = fma2(p1.x, bd, c[j][2]);
                c[j][3] = fma2(p1.y, bd, c[j][3]);
                c[j][4] = fma2(p2.x, bd, c[j][4]);
                c[j][5] = fma2(p2.y, bd, c[j][5]);
                c[j][6] = fma2(p3.x, bd, c[j][6]);
                c[j][7] = fma2(p3.y, bd, c[j][7]);
            }
        }
        if (ci < 7) {
            PV_STV(ci + 1, nxt);
            CP_WAIT(0);
            __syncthreads();
        }
    }

    // partial context: g_ctxp[scid][(b*S + t)*768 + h*64 + d]
    float* P = g_ctxp + (size_t)scid * CTX_ELEMS;
#pragma unroll
    for (int j = 0; j < 4; j++) {
        const int t = t0 + tx * 4 + j;
        float f[16];
#pragma unroll
        for (int i = 0; i < 8; i++) unpack2(c[j][i], f[2 * i], f[2 * i + 1]);
        float* op = &P[((size_t)b * S_DIM + t) * (H_NUM * D_DIM) + h * D_DIM + ty * 16];
        *(float4*)(op + 0)  = make_float4(f[0], f[1], f[2], f[3]);
        *(float4*)(op + 4)  = make_float4(f[4], f[5], f[6], f[7]);
        *(float4*)(op + 8)  = make_float4(f[8], f[9], f[10], f[11]);
        *(float4*)(op + 12) = make_float4(f[12], f[13], f[14], f[15]);
    }
}

// ---------------------------------------------------------------------------
// Kernel 3: reduce the 4 context partials into the output (deterministic).
// ---------------------------------------------------------------------------
__global__ __launch_bounds__(256) void reduce_kernel(float* __restrict__ ctx)
{
    const size_t i4 = ((size_t)blockIdx.x * 256 + threadIdx.x) * 4;
    float4 a = *(const float4*)&g_ctxp[i4];
    float4 b = *(const float4*)&g_ctxp[CTX_ELEMS + i4];
    float4 c = *(const float4*)&g_ctxp[2 * CTX_ELEMS + i4];
    float4 d = *(const float4*)&g_ctxp[3 * CTX_ELEMS + i4];
    float4 r = make_float4((a.x + b.x) + (c.x + d.x),
                           (a.y + b.y) + (c.y + d.y),
                           (a.z + b.z) + (c.z + d.z),
                           (a.w + b.w) + (c.w + d.w));
    *(float4*)&ctx[i4] = r;
}

// ---------------------------------------------------------------------------
extern "C" void kernel_launch(void* const* d_in, const int* in_sizes, int n_in,
                              void* d_out, int out_size)
{
    (void)in_sizes; (void)n_in; (void)out_size;
    const float* Q = (const float*)d_in[0];
    const float* K = (const float*)d_in[1];
    const float* V = (const float*)d_in[2];
    const int* mask = (const int*)d_in[3];

    float* ctx  = (float*)d_out;                 // (B, S, H*D)
    float* attn = ctx + CTX_ELEMS;               // (B, H, S, S)

    cudaFuncSetAttribute(qk_kernel, cudaFuncAttributeMaxDynamicSharedMemorySize, 65536);
    cudaFuncSetAttribute(pv_kernel, cudaFuncAttributeMaxDynamicSharedMemorySize, 51200);

    qk_kernel<<<dim3(8, 8, NBH), 256, 65536>>>(Q, K, mask);
    pv_kernel<<<15360, 128, 51200>>>(V, attn);
    reduce_kernel<<<(unsigned)(CTX_ELEMS / 4 / 256), 256>>>(ctx);
}

// round 5
// speedup vs baseline: 1.7018x; 1.7018x over previous
#include <cuda_runtime.h>

// Shapes (fixed): B=8, H=12, D=64, S=1024
// scores[b,h,s,t] = (1/8) * sum_d K[b,h,d,s] * Q[b,h,d,t]
// mask over t (per b), softmax over t (per (bh,s) row),
// context[b,h,d,t] = sum_s V[b,h,d,s]*attn[b,h,s,t]
// out = concat( context as (B,S,H*D), attn as (B,H,S,S) )
//
// qk_kernel : QK GEMM (FFMA2) -> raw E = exp(score/8)*mask into the attn
//             output region + per-(s, t-block) partial row sums (g_part).
// pv_kernel : per (t-tile, bh): full s-loop GEMM ctx = E x (inv*V) with E
//             double-buffered via cp.async; writes normalized attn in place
//             from smem after each chunk. No scratch partials, no reduce.

#define D_DIM 64
#define S_DIM 1024
#define H_NUM 12
#define B_NUM 8
#define NBH   (B_NUM * H_NUM)
#define CTX_ELEMS ((size_t)B_NUM * S_DIM * H_NUM * D_DIM)   // 6291456

typedef unsigned long long ull;

__device__ __forceinline__ ull pack_dup(float x) {
    ull r; asm("mov.b64 %0, {%1,%2};" : "=l"(r) : "f"(x), "f"(x)); return r;
}
__device__ __forceinline__ void unpack2(ull v, float& lo, float& hi) {
    asm("mov.b64 {%0,%1}, %2;" : "=f"(lo), "=f"(hi) : "l"(v));
}
__device__ __forceinline__ ull fma2(ull a, ull b, ull c) {
    ull d; asm("fma.rn.f32x2 %0, %1, %2, %3;" : "=l"(d) : "l"(a), "l"(b), "l"(c));
    return d;
}
__device__ __forceinline__ unsigned s2u(const void* p) {
    return (unsigned)__cvta_generic_to_shared(p);
}

// Partial row sums from qk: [t_block(8)][bh(96)][s(1024)]
__device__ float g_part[8 * NBH * S_DIM];

// ---------------------------------------------------------------------------
// Kernel 1: QK^T GEMM + exp + mask (identical to the proven R3 version).
// Tile 128(s) x 128(t), K = 64 (d). Micro: 16(s, f32x2 pairs) x 4(t).
// ---------------------------------------------------------------------------
__global__ __launch_bounds__(256, 2) void qk_kernel(
    const float* __restrict__ Q, const float* __restrict__ K,
    const int* __restrict__ mask, float* __restrict__ attn)
{
    const int bh = blockIdx.z;
    const int s0 = blockIdx.y * 128;
    const int t0 = blockIdx.x * 128;
    const float* Kb = K + (size_t)bh * D_DIM * S_DIM;
    const float* Qb = Q + (size_t)bh * D_DIM * S_DIM;

    __shared__ float As[32][128];   // [d_chunk][s]
    __shared__ float Bs[32][128];   // [d_chunk][t]

    const int tid = threadIdx.x;
    const int tx = tid & 31;        // t micro: t0 + tx*4 + j
    const int ty = tid >> 5;        // s micro: s0 + ty*16 + r

    ull c[8][4];
#pragma unroll
    for (int i = 0; i < 8; i++)
#pragma unroll
        for (int j = 0; j < 4; j++) c[i][j] = 0ULL;

#pragma unroll
    for (int ch = 0; ch < 2; ch++) {
#pragma unroll
        for (int j = 0; j < 4; j++) {
            const int lin = tid + j * 256;
            const int row = lin >> 5;
            const int col = (lin & 31) * 4;
            *(float4*)&As[row][col] =
                *(const float4*)&Kb[(size_t)(ch * 32 + row) * S_DIM + s0 + col];
            *(float4*)&Bs[row][col] =
                *(const float4*)&Qb[(size_t)(ch * 32 + row) * S_DIM + t0 + col];
        }
        __syncthreads();
#pragma unroll
        for (int k = 0; k < 32; k++) {
            const ulonglong2 a01 = *(const ulonglong2*)&As[k][ty * 16];
            const ulonglong2 a23 = *(const ulonglong2*)&As[k][ty * 16 + 4];
            const ulonglong2 a45 = *(const ulonglong2*)&As[k][ty * 16 + 8];
            const ulonglong2 a67 = *(const ulonglong2*)&As[k][ty * 16 + 12];
            const float4 bv = *(const float4*)&Bs[k][tx * 4];
            const ull bd0 = pack_dup(bv.x);
            const ull bd1 = pack_dup(bv.y);
            const ull bd2 = pack_dup(bv.z);
            const ull bd3 = pack_dup(bv.w);
            ull a[8] = {a01.x, a01.y, a23.x, a23.y, a45.x, a45.y, a67.x, a67.y};
#pragma unroll
            for (int i = 0; i < 8; i++) {
                c[i][0] = fma2(a[i], bd0, c[i][0]);
                c[i][1] = fma2(a[i], bd1, c[i][1]);
                c[i][2] = fma2(a[i], bd2, c[i][2]);
                c[i][3] = fma2(a[i], bd3, c[i][3]);
            }
        }
        __syncthreads();
    }

    // Epilogue: scale, mask, exp, store raw E, partial row sums.
    const int b = bh / H_NUM;
    const int4 mv = *(const int4*)&mask[b * S_DIM + t0 + tx * 4];
    const float m0 = mv.x ? 1.f : 0.f;
    const float m1 = mv.y ? 1.f : 0.f;
    const float m2 = mv.z ? 1.f : 0.f;
    const float m3 = mv.w ? 1.f : 0.f;

    float rs[16];
    const size_t base = ((size_t)bh * S_DIM + (s0 + ty * 16)) * S_DIM + t0 + tx * 4;
#pragma unroll
    for (int i = 0; i < 8; i++) {
        float l0, h0, l1, h1, l2, h2, l3, h3;
        unpack2(c[i][0], l0, h0);
        unpack2(c[i][1], l1, h1);
        unpack2(c[i][2], l2, h2);
        unpack2(c[i][3], l3, h3);
        float4 e0 = make_float4(__expf(l0 * 0.125f) * m0, __expf(l1 * 0.125f) * m1,
                                __expf(l2 * 0.125f) * m2, __expf(l3 * 0.125f) * m3);
        float4 e1 = make_float4(__expf(h0 * 0.125f) * m0, __expf(h1 * 0.125f) * m1,
                                __expf(h2 * 0.125f) * m2, __expf(h3 * 0.125f) * m3);
        *(float4*)&attn[base + (size_t)(2 * i) * S_DIM] = e0;
        *(float4*)&attn[base + (size_t)(2 * i + 1) * S_DIM] = e1;
        rs[2 * i]     = (e0.x + e0.y) + (e0.z + e0.w);
        rs[2 * i + 1] = (e1.x + e1.y) + (e1.z + e1.w);
    }
#pragma unroll
    for (int r = 0; r < 16; r++) {
        float v = rs[r];
#pragma unroll
        for (int o = 16; o > 0; o >>= 1)
            v += __shfl_xor_sync(0xffffffffu, v, o);
        rs[r] = v;
    }
    if (tx == 0) {
        float* pp = &g_part[((blockIdx.x * NBH + bh) << 10) + s0 + ty * 16];
#pragma unroll
        for (int r4 = 0; r4 < 4; r4++)
            *(float4*)&pp[r4 * 4] =
                make_float4(rs[r4 * 4], rs[r4 * 4 + 1], rs[r4 * 4 + 2], rs[r4 * 4 + 3]);
    }
}

// ---------------------------------------------------------------------------
// Kernel 2: PV GEMM + attn normalize, full s-loop. 128 threads, tile
// 64(d) x 128(t), 32 s-chunks of 32, E double-buffered via cp.async (raw),
// inv folded into V; normalized attn written from smem after each chunk.
// Micro: 16(d, f32x2 pairs) x 4(t).
// ---------------------------------------------------------------------------
__global__ __launch_bounds__(128, 4) void pv_kernel(
    const float* __restrict__ V, float* __restrict__ attn,
    float* __restrict__ ctx)
{
    extern __shared__ float smp[];
    float (*Es)[32][128] = (float(*)[32][128])smp;            // [2][32][128] raw E
    float (*Vs)[32][68]  = (float(*)[32][68])(smp + 8192);    // [2][32][68] inv*V
    float* invs          = smp + 8192 + 4352;                  // [1024]

    const int bh = blockIdx.y;
    const int t0 = blockIdx.x * 128;
    const int b = bh / H_NUM;
    const int h = bh - b * H_NUM;
    const float* Vb = V + (size_t)bh * D_DIM * S_DIM;
    float* Ab = attn + (size_t)bh * S_DIM * S_DIM;

    const int tid = threadIdx.x;
    const int tx = tid & 31;          // t micro: t0 + tx*4 + j
    const int ty = tid >> 5;          // d micro: ty*16 + 2i(+1)
    const int vd = tid & 63;          // V: d row
    const int vhalf = tid >> 6;       // V: s half (0/1) of 32-chunk

    // 1/rowsum for all 1024 s of this bh (deterministic 8-way sum).
#pragma unroll
    for (int j = 0; j < 8; j++) {
        const int s = tid + j * 128;
        float sum = 0.f;
#pragma unroll
        for (int tb = 0; tb < 8; tb++)
            sum += g_part[((tb * NBH + bh) << 10) + s];
        invs[s] = 1.0f / sum;
    }
    __syncthreads();

#define PV_CPE(ci, buf)                                                        \
    {                                                                          \
        _Pragma("unroll")                                                      \
        for (int u = 0; u < 8; u++) {                                          \
            const int id = tid + u * 128;                                      \
            const int row = id >> 5;                                           \
            const int cc = (id & 31) * 4;                                      \
            asm volatile("cp.async.cg.shared.global [%0], [%1], 16;" ::        \
                "r"(s2u(&Es[buf][row][cc])),                                   \
                "l"(&Ab[(size_t)((ci) * 32 + row) * S_DIM + t0 + cc]));        \
        }                                                                      \
        asm volatile("cp.async.commit_group;");                                \
    }

    float4 vr[4];
#define PV_LDV(ci)                                                             \
    {                                                                          \
        const float* vp = &Vb[(size_t)vd * S_DIM + (ci) * 32 + vhalf * 16];    \
        vr[0] = *(const float4*)(vp + 0);                                      \
        vr[1] = *(const float4*)(vp + 4);                                      \
        vr[2] = *(const float4*)(vp + 8);                                      \
        vr[3] = *(const float4*)(vp + 12);                                     \
    }

#define PV_STV(ci, buf)                                                        \
    {                                                                          \
        _Pragma("unroll")                                                      \
        for (int q = 0; q < 4; q++) {                                          \
            const int sl = vhalf * 16 + q * 4;                                 \
            const float4 iv = *(const float4*)&invs[(ci) * 32 + sl];           \
            Vs[buf][sl + 0][vd] = vr[q].x * iv.x;                              \
            Vs[buf][sl + 1][vd] = vr[q].y * iv.y;                              \
            Vs[buf][sl + 2][vd] = vr[q].z * iv.z;                              \
            Vs[buf][sl + 3][vd] = vr[q].w * iv.w;                              \
        }                                                                      \
    }

    // prologue: chunk 0
    PV_CPE(0, 0);
    PV_LDV(0);
    PV_STV(0, 0);
    asm volatile("cp.async.wait_group 0;");
    __syncthreads();

    ull c[4][8];   // [t j][d pair i]
#pragma unroll
    for (int j = 0; j < 4; j++)
#pragma unroll
        for (int i = 0; i < 8; i++) c[j][i] = 0ULL;

    for (int ci = 0; ci < 32; ci++) {
        const int cur = ci & 1, nxt = cur ^ 1;
        if (ci < 31) { PV_CPE(ci + 1, nxt); PV_LDV(ci + 1); }
        // compute current chunk (V smem reads are warp-broadcast)
#pragma unroll
        for (int k = 0; k < 32; k++) {
            const ulonglong2 p0 = *(const ulonglong2*)&Vs[cur][k][ty * 16];
            const ulonglong2 p1 = *(const ulonglong2*)&Vs[cur][k][ty * 16 + 4];
            const ulonglong2 p2 = *(const ulonglong2*)&Vs[cur][k][ty * 16 + 8];
            const ulonglong2 p3 = *(const ulonglong2*)&Vs[cur][k][ty * 16 + 12];
            const float4 bv = *(const float4*)&Es[cur][k][tx * 4];
            const ull bd0 = pack_dup(bv.x);
            const ull bd1 = pack_dup(bv.y);
            const ull bd2 = pack_dup(bv.z);
            const ull bd3 = pack_dup(bv.w);
#pragma unroll
            for (int j = 0; j < 4; j++) {
                const ull bd = (j == 0) ? bd0 : (j == 1) ? bd1 : (j == 2) ? bd2 : bd3;
                c[j][0] = fma2(p0.x, bd, c[j][0]);
                c[j][1] = fma2(p0.y, bd, c[j][1]);
                c[j][2] = fma2(p1.x, bd, c[j][2]);
                c[j][3] = fma2(p1.y, bd, c[j][3]);
                c[j][4] = fma2(p2.x, bd, c[j][4]);
                c[j][5] = fma2(p2.y, bd, c[j][5]);
                c[j][6] = fma2(p3.x, bd, c[j][6]);
                c[j][7] = fma2(p3.y, bd, c[j][7]);
            }
        }
        // write normalized attn for this chunk from smem (in place over raw E)
#pragma unroll
        for (int u = 0; u < 8; u++) {
            const int id = tid + u * 128;
            const int row = id >> 5;
            const int cc = (id & 31) * 4;
            const float iv = invs[ci * 32 + row];
            float4 e = *(const float4*)&Es[cur][row][cc];
            e.x *= iv; e.y *= iv; e.z *= iv; e.w *= iv;
            *(float4*)&Ab[(size_t)(ci * 32 + row) * S_DIM + t0 + cc] = e;
        }
        if (ci < 31) {
            PV_STV(ci + 1, nxt);
            asm volatile("cp.async.wait_group 0;");
            __syncthreads();
        }
    }

    // context out: ctx[(b*S + t)*768 + h*64 + d]
#pragma unroll
    for (int j = 0; j < 4; j++) {
        const int t = t0 + tx * 4 + j;
        float f[16];
#pragma unroll
        for (int i = 0; i < 8; i++) unpack2(c[j][i], f[2 * i], f[2 * i + 1]);
        float* op = &ctx[((size_t)b * S_DIM + t) * (H_NUM * D_DIM) + h * D_DIM + ty * 16];
        *(float4*)(op + 0)  = make_float4(f[0], f[1], f[2], f[3]);
        *(float4*)(op + 4)  = make_float4(f[4], f[5], f[6], f[7]);
        *(float4*)(op + 8)  = make_float4(f[8], f[9], f[10], f[11]);
        *(float4*)(op + 12) = make_float4(f[12], f[13], f[14], f[15]);
    }
}

// ---------------------------------------------------------------------------
extern "C" void kernel_launch(void* const* d_in, const int* in_sizes, int n_in,
                              void* d_out, int out_size)
{
    (void)in_sizes; (void)n_in; (void)out_size;
    const float* Q = (const float*)d_in[0];
    const float* K = (const float*)d_in[1];
    const float* V = (const float*)d_in[2];
    const int* mask = (const int*)d_in[3];

    float* ctx  = (float*)d_out;                 // (B, S, H*D)
    float* attn = ctx + CTX_ELEMS;               // (B, H, S, S)

    static int smem_set = 0;
    if (!smem_set) {
        cudaFuncSetAttribute(pv_kernel, cudaFuncAttributeMaxDynamicSharedMemorySize,
                             (2 * 32 * 128 + 2 * 32 * 68 + 1024) * 4);
        smem_set = 1;
    }

    qk_kernel<<<dim3(8, 8, NBH), 256>>>(Q, K, mask, attn);
    pv_kernel<<<dim3(8, NBH), 128, (2 * 32 * 128 + 2 * 32 * 68 + 1024) * 4>>>(V, attn, ctx);
}

// round 8
// speedup vs baseline: 1.7236x; 1.0128x over previous
#include <cuda_runtime.h>
#include <cuda_bf16.h>
#include <cstdint>

// Shapes (fixed): B=8, H=12, D=64, S=1024
// scores[b,h,s,t] = (1/8) * sum_d K[b,h,d,s] * Q[b,h,d,t]
// mask over t (per b), softmax over t, context[b,h,d,t] = sum_s V[b,h,d,s]*attn[b,h,s,t]
// out = concat( context as (B,S,H*D), attn as (B,H,S,S) )
//
// convert_kernel : K,Q fp32 [bh][d][s] -> bf16 hi/lo planes [bh][s][d].
// qk_mma_kernel  : warp-level mma.sync bf16-split (3 passes) QK GEMM;
//                  epilogue E = exp(score/8)*mask -> attn region + row sums.
// pv_kernel      : unchanged R5 FFMA2 GEMM, ctx = E x (inv*V), normalizes attn.

#define D_DIM 64
#define S_DIM 1024
#define H_NUM 12
#define B_NUM 8
#define NBH   (B_NUM * H_NUM)
#define CTX_ELEMS ((size_t)B_NUM * S_DIM * H_NUM * D_DIM)   // 6291456
#define PLANE_ELEMS (NBH * S_DIM * D_DIM)                    // 6291456

typedef unsigned long long ull;

__device__ __forceinline__ ull pack_dup(float x) {
    ull r; asm("mov.b64 %0, {%1,%2};" : "=l"(r) : "f"(x), "f"(x)); return r;
}
__device__ __forceinline__ void unpack2(ull v, float& lo, float& hi) {
    asm("mov.b64 {%0,%1}, %2;" : "=f"(lo), "=f"(hi) : "l"(v));
}
__device__ __forceinline__ ull fma2(ull a, ull b, ull c) {
    ull d; asm("fma.rn.f32x2 %0, %1, %2, %3;" : "=l"(d) : "l"(a), "l"(b), "l"(c));
    return d;
}
__device__ __forceinline__ unsigned s2u(const void* p) {
    return (unsigned)__cvta_generic_to_shared(p);
}
__device__ __forceinline__ uint32_t swz128(uint32_t off) {
    return off ^ ((off >> 3) & 0x70);
}
__device__ __forceinline__ void ldsm4(uint32_t* r, uint32_t addr) {
    asm volatile("ldmatrix.sync.aligned.m8n8.x4.shared.b16 {%0,%1,%2,%3}, [%4];"
                 : "=r"(r[0]), "=r"(r[1]), "=r"(r[2]), "=r"(r[3]) : "r"(addr));
}
__device__ __forceinline__ void mma16816(float* c, const uint32_t* a, const uint32_t* b) {
    asm volatile(
        "mma.sync.aligned.m16n8k16.row.col.f32.bf16.bf16.f32 "
        "{%0,%1,%2,%3}, {%4,%5,%6,%7}, {%8,%9}, {%0,%1,%2,%3};"
        : "+f"(c[0]), "+f"(c[1]), "+f"(c[2]), "+f"(c[3])
        : "r"(a[0]), "r"(a[1]), "r"(a[2]), "r"(a[3]), "r"(b[0]), "r"(b[1]));
}

// ---------------- global scratch ----------------
// planes: 0=K_hi 1=K_lo 2=Q_hi 3=Q_lo, each [bh][s][d] bf16
__device__ __nv_bfloat16 g_cvt[4 * PLANE_ELEMS];
// Partial row sums: [t_block(8)][bh(96)][s(1024)]
__device__ float g_part[8 * NBH * S_DIM];

// ---------------------------------------------------------------------------
// convert_kernel: transpose+split K,Q fp32 [bh][64 d][1024 s] -> bf16 hi/lo
// planes [bh][s][64 d]. grid (16 s-tiles, 96 bh, 2 tensors), 256 threads.
// ---------------------------------------------------------------------------
__global__ __launch_bounds__(256) void convert_kernel(
    const float* __restrict__ K, const float* __restrict__ Q)
{
    const int z = blockIdx.z;                 // 0 = K, 1 = Q
    const int bh = blockIdx.y;
    const int s0 = blockIdx.x * 64;
    const float* X = z ? Q : K;
    __nv_bfloat16* hiP = g_cvt + (size_t)(z * 2) * PLANE_ELEMS;
    __nv_bfloat16* loP = g_cvt + (size_t)(z * 2 + 1) * PLANE_ELEMS;

    __shared__ float t[64][68];
    const int tid = threadIdx.x;

#pragma unroll
    for (int j = 0; j < 4; j++) {
        const int d = (tid >> 4) + j * 16;
        const int s = (tid & 15) * 4;
        const float4 v = *(const float4*)&X[(((size_t)bh * 64 + d) << 10) + s0 + s];
        t[d][s + 0] = v.x; t[d][s + 1] = v.y; t[d][s + 2] = v.z; t[d][s + 3] = v.w;
    }
    __syncthreads();

    const int sl = tid >> 2;
    const int dq = (tid & 3) * 16;
    __align__(16) __nv_bfloat16 hb[16], lb[16];
#pragma unroll
    for (int q = 0; q < 16; q++) {
        const float x = t[dq + q][sl];
        const __nv_bfloat16 h = __float2bfloat16_rn(x);
        hb[q] = h;
        lb[q] = __float2bfloat16_rn(x - __bfloat162float(h));
    }
    const size_t o = ((size_t)bh * S_DIM + s0 + sl) * D_DIM + dq;
    *(uint4*)&hiP[o]     = *(const uint4*)&hb[0];
    *(uint4*)&hiP[o + 8] = *(const uint4*)&hb[8];
    *(uint4*)&loP[o]     = *(const uint4*)&lb[0];
    *(uint4*)&loP[o + 8] = *(const uint4*)&lb[8];
}

// ---------------------------------------------------------------------------
// qk_mma_kernel: 128(s) x 128(t) tile per CTA via mma.sync bf16-split.
// 8 warps: wm = w&3 (4 along s), wn = w>>2 (2 along t). Warp tile 32x64.
// smem: [0,16K) A_hi | [16K,32K) A_lo | [32K,48K) B_hi | [48K,64K) B_lo
//       (SW128 swizzled, 128B rows of 64 bf16)
// epilogue staging reuses [0, 67584) as float Es[128][132]; fmask at 67584.
// ---------------------------------------------------------------------------
#define QK_DSMEM (1024 + 68096)

__global__ __launch_bounds__(256) void qk_mma_kernel(
    const int* __restrict__ mask, float* __restrict__ attn)
{
    extern __shared__ char raw[];
    char* SB = (char*)(((uintptr_t)raw + 1023) & ~(uintptr_t)1023);
    const uint32_t sb = s2u(SB);
    float* fmask = (float*)(SB + 67584);

    const int bh = blockIdx.z;
    const int s0 = blockIdx.y * 128;
    const int t0 = blockIdx.x * 128;
    const int b = bh / H_NUM;
    const int tid = threadIdx.x;
    const int w = tid >> 5, lane = tid & 31;
    const int wm = w & 3, wn = w >> 2;

    // stage 4 tiles (A_hi, A_lo, B_hi, B_lo) via 16B cp.async into SW128 layout
#pragma unroll
    for (int u = 0; u < 16; u++) {
        const int id = tid + u * 256;
        const int T = id >> 10;            // tile 0..3
        const int r = (id >> 3) & 127;     // row
        const int c = id & 7;              // 16B chunk
        const int row0 = (T >= 2) ? t0 : s0;
        const __nv_bfloat16* src = g_cvt + (size_t)T * PLANE_ELEMS
            + ((size_t)bh * S_DIM + row0 + r) * D_DIM + c * 8;
        const uint32_t dst = sb + T * 16384 + swz128(r * 128 + c * 16);
        asm volatile("cp.async.cg.shared.global [%0], [%1], 16;" :: "r"(dst), "l"(src));
    }
    asm volatile("cp.async.commit_group;");

    if (tid < 128) fmask[tid] = mask[b * S_DIM + t0 + tid] ? 1.0f : 0.0f;

    asm volatile("cp.async.wait_group 0;");
    __syncthreads();

    float c[2][8][4];
#pragma unroll
    for (int m = 0; m < 2; m++)
#pragma unroll
        for (int n = 0; n < 8; n++)
#pragma unroll
            for (int i = 0; i < 4; i++) c[m][n][i] = 0.f;

    const int q8 = lane >> 3, r8 = lane & 7;

#pragma unroll
    for (int ks = 0; ks < 4; ks++) {
        uint32_t ah[2][4], al[2][4], bh2[8][2], bl2[8][2];
        // A fragments (rows = s): non-trans ldmatrix, pairs contiguous along k(d)
#pragma unroll
        for (int m = 0; m < 2; m++) {
            const int rowA = wm * 32 + m * 16 + ((q8 & 1) << 3) + r8;
            const uint32_t off = swz128(rowA * 128 + (2 * ks + (q8 >> 1)) * 16);
            ldsm4(ah[m], sb + off);
            ldsm4(al[m], sb + 16384 + off);
        }
        // B fragments (rows = t = n, cols = d = k): ALSO non-trans — fragment b
        // needs pairs contiguous along k for fixed n, which is exactly the
        // row-pair distribution of ldmatrix on our [t][d] tile.
        // q8 bit0 -> k-chunk (+16B), q8 bit1 -> n+8.
#pragma unroll
        for (int np = 0; np < 4; np++) {
            const int rowB = wn * 64 + np * 16 + ((q8 >> 1) << 3) + r8;
            const uint32_t off = swz128(rowB * 128 + (2 * ks + (q8 & 1)) * 16);
            uint32_t tmp[4];
            ldsm4(tmp, sb + 32768 + off);
            bh2[np * 2][0] = tmp[0]; bh2[np * 2][1] = tmp[1];
            bh2[np * 2 + 1][0] = tmp[2]; bh2[np * 2 + 1][1] = tmp[3];
            ldsm4(tmp, sb + 49152 + off);
            bl2[np * 2][0] = tmp[0]; bl2[np * 2][1] = tmp[1];
            bl2[np * 2 + 1][0] = tmp[2]; bl2[np * 2 + 1][1] = tmp[3];
        }
        // 3 split passes: hi*hi + hi*lo + lo*hi
#pragma unroll
        for (int m = 0; m < 2; m++)
#pragma unroll
            for (int n = 0; n < 8; n++) {
                mma16816(c[m][n], ah[m], bh2[n]);
                mma16816(c[m][n], ah[m], bl2[n]);
                mma16816(c[m][n], al[m], bh2[n]);
            }
    }

    __syncthreads();   // tiles free; reuse as staging

    // fragment epilogue: exp * mask -> Es staging
    float* Es = (float*)SB;    // [128][132]
    const int g4 = lane >> 2, l4 = lane & 3;
#pragma unroll
    for (int m = 0; m < 2; m++)
#pragma unroll
        for (int n = 0; n < 8; n++) {
            const int rm = wm * 32 + m * 16 + g4;
            const int cn = wn * 64 + n * 8 + l4 * 2;
            const float f0 = fmask[cn], f1 = fmask[cn + 1];
            float2 e01, e23;
            e01.x = __expf(c[m][n][0] * 0.125f) * f0;
            e01.y = __expf(c[m][n][1] * 0.125f) * f1;
            e23.x = __expf(c[m][n][2] * 0.125f) * f0;
            e23.y = __expf(c[m][n][3] * 0.125f) * f1;
            *(float2*)&Es[rm * 132 + cn] = e01;
            *(float2*)&Es[(rm + 8) * 132 + cn] = e23;
        }
    __syncthreads();

    // coalesced store + row sums: one row per warp per pass
#pragma unroll
    for (int pass = 0; pass < 16; pass++) {
        const int row = w + pass * 8;
        const float4 v = *(const float4*)&Es[row * 132 + lane * 4];
        float rs = (v.x + v.y) + (v.z + v.w);
#pragma unroll
        for (int o = 16; o > 0; o >>= 1)
            rs += __shfl_xor_sync(0xffffffffu, rs, o);
        *(float4*)&attn[((size_t)(bh * S_DIM + s0 + row)) * S_DIM + t0 + lane * 4] = v;
        if (lane == 0)
            g_part[((blockIdx.x * NBH + bh) << 10) + s0 + row] = rs;
    }
}

// ---------------------------------------------------------------------------
// pv_kernel: unchanged R5. 128 threads, tile 64(d) x 128(t), 32 s-chunks,
// E double-buffered via cp.async (raw), inv folded into V; writes normalized
// attn from smem after each chunk. Micro: 16(d, f32x2 pairs) x 4(t).
// ---------------------------------------------------------------------------
__global__ __launch_bounds__(128, 4) void pv_kernel(
    const float* __restrict__ V, float* __restrict__ attn,
    float* __restrict__ ctx)
{
    extern __shared__ float smp[];
    float (*Es)[32][128] = (float(*)[32][128])smp;            // [2][32][128] raw E
    float (*Vs)[32][68]  = (float(*)[32][68])(smp + 8192);    // [2][32][68] inv*V
    float* invs          = smp + 8192 + 4352;                  // [1024]

    const int bh = blockIdx.y;
    const int t0 = blockIdx.x * 128;
    const int b = bh / H_NUM;
    const int h = bh - b * H_NUM;
    const float* Vb = V + (size_t)bh * D_DIM * S_DIM;
    float* Ab = attn + (size_t)bh * S_DIM * S_DIM;

    const int tid = threadIdx.x;
    const int tx = tid & 31;
    const int ty = tid >> 5;
    const int vd = tid & 63;
    const int vhalf = tid >> 6;

#pragma unroll
    for (int j = 0; j < 8; j++) {
        const int s = tid + j * 128;
        float sum = 0.f;
#pragma unroll
        for (int tb = 0; tb < 8; tb++)
            sum += g_part[((tb * NBH + bh) << 10) + s];
        invs[s] = 1.0f / sum;
    }
    __syncthreads();

#define PV_CPE(ci, buf)                                                        \
    {                                                                          \
        _Pragma("unroll")                                                      \
        for (int u = 0; u < 8; u++) {                                          \
            const int id = tid + u * 128;                                      \
            const int row = id >> 5;                                           \
            const int cc = (id & 31) * 4;                                      \
            asm volatile("cp.async.cg.shared.global [%0], [%1], 16;" ::        \
                "r"(s2u(&Es[buf][row][cc])),                                   \
                "l"(&Ab[(size_t)((ci) * 32 + row) * S_DIM + t0 + cc]));        \
        }                                                                      \
        asm volatile("cp.async.commit_group;");                                \
    }

    float4 vr[4];
#define PV_LDV(ci)                                                             \
    {                                                                          \
        const float* vp = &Vb[(size_t)vd * S_DIM + (ci) * 32 + vhalf * 16];    \
        vr[0] = *(const float4*)(vp + 0);                                      \
        vr[1] = *(const float4*)(vp + 4);                                      \
        vr[2] = *(const float4*)(vp + 8);                                      \
        vr[3] = *(const float4*)(vp + 12);                                     \
    }

#define PV_STV(ci, buf)                                                        \
    {                                                                          \
        _Pragma("unroll")                                                      \
        for (int q = 0; q < 4; q++) {                                          \
            const int sl = vhalf * 16 + q * 4;                                 \
            const float4 iv = *(const float4*)&invs[(ci) * 32 + sl];           \
            Vs[buf][sl + 0][vd] = vr[q].x * iv.x;                              \
            Vs[buf][sl + 1][vd] = vr[q].y * iv.y;                              \
            Vs[buf][sl + 2][vd] = vr[q].z * iv.z;                              \
            Vs[buf][sl + 3][vd] = vr[q].w * iv.w;                              \
        }                                                                      \
    }

    PV_CPE(0, 0);
    PV_LDV(0);
    PV_STV(0, 0);
    asm volatile("cp.async.wait_group 0;");
    __syncthreads();

    ull c[4][8];
#pragma unroll
    for (int j = 0; j < 4; j++)
#pragma unroll
        for (int i = 0; i < 8; i++) c[j][i] = 0ULL;

    for (int ci = 0; ci < 32; ci++) {
        const int cur = ci & 1, nxt = cur ^ 1;
        if (ci < 31) { PV_CPE(ci + 1, nxt); PV_LDV(ci + 1); }
#pragma unroll
        for (int k = 0; k < 32; k++) {
            const ulonglong2 p0 = *(const ulonglong2*)&Vs[cur][k][ty * 16];
            const ulonglong2 p1 = *(const ulonglong2*)&Vs[cur][k][ty * 16 + 4];
            const ulonglong2 p2 = *(const ulonglong2*)&Vs[cur][k][ty * 16 + 8];
            const ulonglong2 p3 = *(const ulonglong2*)&Vs[cur][k][ty * 16 + 12];
            const float4 bv = *(const float4*)&Es[cur][k][tx * 4];
            const ull bd0 = pack_dup(bv.x);
            const ull bd1 = pack_dup(bv.y);
            const ull bd2 = pack_dup(bv.z);
            const ull bd3 = pack_dup(bv.w);
#pragma unroll
            for (int j = 0; j < 4; j++) {
                const ull bd = (j == 0) ? bd0 : (j == 1) ? bd1 : (j == 2) ? bd2 : bd3;
                c[j][0] = fma2(p0.x, bd, c[j][0]);
                c[j][1] = fma2(p0.y, bd, c[j][1]);
                c[j][2] = fma2(p1.x, bd, c[j][2]);
                c[j][3] = fma2(p1.y, bd, c[j][3]);
                c[j][4] = fma2(p2.x, bd, c[j][4]);
                c[j][5] = fma2(p2.y, bd, c[j][5]);
                c[j][6] = fma2(p3.x, bd, c[j][6]);
                c[j][7] = fma2(p3.y, bd, c[j][7]);
            }
        }
#pragma unroll
        for (int u = 0; u < 8; u++) {
            const int id = tid + u * 128;
            const int row = id >> 5;
            const int cc = (id & 31) * 4;
            const float iv = invs[ci * 32 + row];
            float4 e = *(const float4*)&Es[cur][row][cc];
            e.x *= iv; e.y *= iv; e.z *= iv; e.w *= iv;
            *(float4*)&Ab[(size_t)(ci * 32 + row) * S_DIM + t0 + cc] = e;
        }
        if (ci < 31) {
            PV_STV(ci + 1, nxt);
            asm volatile("cp.async.wait_group 0;");
            __syncthreads();
        }
    }

#pragma unroll
    for (int j = 0; j < 4; j++) {
        const int t = t0 + tx * 4 + j;
        float f[16];
#pragma unroll
        for (int i = 0; i < 8; i++) unpack2(c[j][i], f[2 * i], f[2 * i + 1]);
        float* op = &ctx[((size_t)b * S_DIM + t) * (H_NUM * D_DIM) + h * D_DIM + ty * 16];
        *(float4*)(op + 0)  = make_float4(f[0], f[1], f[2], f[3]);
        *(float4*)(op + 4)  = make_float4(f[4], f[5], f[6], f[7]);
        *(float4*)(op + 8)  = make_float4(f[8], f[9], f[10], f[11]);
        *(float4*)(op + 12) = make_float4(f[12], f[13], f[14], f[15]);
    }
}

// ---------------------------------------------------------------------------
extern "C" void kernel_launch(void* const* d_in, const int* in_sizes, int n_in,
                              void* d_out, int out_size)
{
    (void)in_sizes; (void)n_in; (void)out_size;
    const float* Q = (const float*)d_in[0];
    const float* K = (const float*)d_in[1];
    const float* V = (const float*)d_in[2];
    const int* mask = (const int*)d_in[3];

    float* ctx  = (float*)d_out;                 // (B, S, H*D)
    float* attn = ctx + CTX_ELEMS;               // (B, H, S, S)

    static int attr_set = 0;
    if (!attr_set) {
        cudaFuncSetAttribute(qk_mma_kernel, cudaFuncAttributeMaxDynamicSharedMemorySize,
                             QK_DSMEM);
        cudaFuncSetAttribute(pv_kernel, cudaFuncAttributeMaxDynamicSharedMemorySize,
                             (2 * 32 * 128 + 2 * 32 * 68 + 1024) * 4);
        attr_set = 1;
    }

    convert_kernel<<<dim3(16, NBH, 2), 256>>>(K, Q);
    qk_mma_kernel<<<dim3(8, 8, NBH), 256, QK_DSMEM>>>(mask, attn);
    pv_kernel<<<dim3(8, NBH), 128, (2 * 32 * 128 + 2 * 32 * 68 + 1024) * 4>>>(V, attn, ctx);
}

// round 11
// speedup vs baseline: 1.8119x; 1.0512x over previous
#include <cuda_runtime.h>
#include <cuda_bf16.h>
#include <cstdint>

// Shapes (fixed): B=8, H=12, D=64, S=1024
// scores[b,h,s,t] = (1/8) * sum_d K[b,h,d,s] * Q[b,h,d,t]
// mask over t (per b), softmax over t, context[b,h,d,t] = sum_s V[b,h,d,s]*attn[b,h,s,t]
// out = concat( context as (B,S,H*D), attn as (B,H,S,S) )
//
// convert_kernel : K,Q fp32 [bh][d][s] -> bf16 hi/lo planes [bh][s][d]. (R8)
// qk_mma_kernel  : mma.sync bf16-split QK GEMM -> raw fp32 E + row sums. (R8)
// pv_mma_kernel  : mma.sync bf16-split PV GEMM. Reads fp32 E tiles, writes
//                  normalized attn (fp32 path), splits E and inv*V to bf16
//                  hi/lo in smem, 3-pass MMA. (R9 + smem-size fix: 64512)

#define D_DIM 64
#define S_DIM 1024
#define H_NUM 12
#define B_NUM 8
#define NBH   (B_NUM * H_NUM)
#define CTX_ELEMS ((size_t)B_NUM * S_DIM * H_NUM * D_DIM)   // 6291456
#define PLANE_ELEMS (NBH * S_DIM * D_DIM)                    // 6291456

typedef unsigned long long ull;

__device__ __forceinline__ unsigned s2u(const void* p) {
    return (unsigned)__cvta_generic_to_shared(p);
}
__device__ __forceinline__ uint32_t swz128(uint32_t off) {
    return off ^ ((off >> 3) & 0x70);
}
__device__ __forceinline__ void ldsm4(uint32_t* r, uint32_t addr) {
    asm volatile("ldmatrix.sync.aligned.m8n8.x4.shared.b16 {%0,%1,%2,%3}, [%4];"
                 : "=r"(r[0]), "=r"(r[1]), "=r"(r[2]), "=r"(r[3]) : "r"(addr));
}
__device__ __forceinline__ void ldsm4t(uint32_t* r, uint32_t addr) {
    asm volatile("ldmatrix.sync.aligned.m8n8.x4.trans.shared.b16 {%0,%1,%2,%3}, [%4];"
                 : "=r"(r[0]), "=r"(r[1]), "=r"(r[2]), "=r"(r[3]) : "r"(addr));
}
__device__ __forceinline__ void mma16816(float* c, const uint32_t* a, const uint32_t* b) {
    asm volatile(
        "mma.sync.aligned.m16n8k16.row.col.f32.bf16.bf16.f32 "
        "{%0,%1,%2,%3}, {%4,%5,%6,%7}, {%8,%9}, {%0,%1,%2,%3};"
        : "+f"(c[0]), "+f"(c[1]), "+f"(c[2]), "+f"(c[3])
        : "r"(a[0]), "r"(a[1]), "r"(a[2]), "r"(a[3]), "r"(b[0]), "r"(b[1]));
}

// ---------------- global scratch ----------------
// planes: 0=K_hi 1=K_lo 2=Q_hi 3=Q_lo, each [bh][s][d] bf16
__device__ __nv_bfloat16 g_cvt[4 * PLANE_ELEMS];
// Partial row sums: [t_block(8)][bh(96)][s(1024)]
__device__ float g_part[8 * NBH * S_DIM];

// ---------------------------------------------------------------------------
// convert_kernel (unchanged R8)
// ---------------------------------------------------------------------------
__global__ __launch_bounds__(256) void convert_kernel(
    const float* __restrict__ K, const float* __restrict__ Q)
{
    const int z = blockIdx.z;
    const int bh = blockIdx.y;
    const int s0 = blockIdx.x * 64;
    const float* X = z ? Q : K;
    __nv_bfloat16* hiP = g_cvt + (size_t)(z * 2) * PLANE_ELEMS;
    __nv_bfloat16* loP = g_cvt + (size_t)(z * 2 + 1) * PLANE_ELEMS;

    __shared__ float t[64][68];
    const int tid = threadIdx.x;

#pragma unroll
    for (int j = 0; j < 4; j++) {
        const int d = (tid >> 4) + j * 16;
        const int s = (tid & 15) * 4;
        const float4 v = *(const float4*)&X[(((size_t)bh * 64 + d) << 10) + s0 + s];
        t[d][s + 0] = v.x; t[d][s + 1] = v.y; t[d][s + 2] = v.z; t[d][s + 3] = v.w;
    }
    __syncthreads();

    const int sl = tid >> 2;
    const int dq = (tid & 3) * 16;
    __align__(16) __nv_bfloat16 hb[16], lb[16];
#pragma unroll
    for (int q = 0; q < 16; q++) {
        const float x = t[dq + q][sl];
        const __nv_bfloat16 h = __float2bfloat16_rn(x);
        hb[q] = h;
        lb[q] = __float2bfloat16_rn(x - __bfloat162float(h));
    }
    const size_t o = ((size_t)bh * S_DIM + s0 + sl) * D_DIM + dq;
    *(uint4*)&hiP[o]     = *(const uint4*)&hb[0];
    *(uint4*)&hiP[o + 8] = *(const uint4*)&hb[8];
    *(uint4*)&loP[o]     = *(const uint4*)&lb[0];
    *(uint4*)&loP[o + 8] = *(const uint4*)&lb[8];
}

// ---------------------------------------------------------------------------
// qk_mma_kernel (unchanged R8)
// ---------------------------------------------------------------------------
#define QK_DSMEM (1024 + 68096)

__global__ __launch_bounds__(256) void qk_mma_kernel(
    const int* __restrict__ mask, float* __restrict__ attn)
{
    extern __shared__ char raw[];
    char* SB = (char*)(((uintptr_t)raw + 1023) & ~(uintptr_t)1023);
    const uint32_t sb = s2u(SB);
    float* fmask = (float*)(SB + 67584);

    const int bh = blockIdx.z;
    const int s0 = blockIdx.y * 128;
    const int t0 = blockIdx.x * 128;
    const int b = bh / H_NUM;
    const int tid = threadIdx.x;
    const int w = tid >> 5, lane = tid & 31;
    const int wm = w & 3, wn = w >> 2;

#pragma unroll
    for (int u = 0; u < 16; u++) {
        const int id = tid + u * 256;
        const int T = id >> 10;
        const int r = (id >> 3) & 127;
        const int c = id & 7;
        const int row0 = (T >= 2) ? t0 : s0;
        const __nv_bfloat16* src = g_cvt + (size_t)T * PLANE_ELEMS
            + ((size_t)bh * S_DIM + row0 + r) * D_DIM + c * 8;
        const uint32_t dst = sb + T * 16384 + swz128(r * 128 + c * 16);
        asm volatile("cp.async.cg.shared.global [%0], [%1], 16;" :: "r"(dst), "l"(src));
    }
    asm volatile("cp.async.commit_group;");

    if (tid < 128) fmask[tid] = mask[b * S_DIM + t0 + tid] ? 1.0f : 0.0f;

    asm volatile("cp.async.wait_group 0;");
    __syncthreads();

    float c[2][8][4];
#pragma unroll
    for (int m = 0; m < 2; m++)
#pragma unroll
        for (int n = 0; n < 8; n++)
#pragma unroll
            for (int i = 0; i < 4; i++) c[m][n][i] = 0.f;

    const int q8 = lane >> 3, r8 = lane & 7;

#pragma unroll
    for (int ks = 0; ks < 4; ks++) {
        uint32_t ah[2][4], al[2][4], bh2[8][2], bl2[8][2];
#pragma unroll
        for (int m = 0; m < 2; m++) {
            const int rowA = wm * 32 + m * 16 + ((q8 & 1) << 3) + r8;
            const uint32_t off = swz128(rowA * 128 + (2 * ks + (q8 >> 1)) * 16);
            ldsm4(ah[m], sb + off);
            ldsm4(al[m], sb + 16384 + off);
        }
#pragma unroll
        for (int np = 0; np < 4; np++) {
            const int rowB = wn * 64 + np * 16 + ((q8 >> 1) << 3) + r8;
            const uint32_t off = swz128(rowB * 128 + (2 * ks + (q8 & 1)) * 16);
            uint32_t tmp[4];
            ldsm4(tmp, sb + 32768 + off);
            bh2[np * 2][0] = tmp[0]; bh2[np * 2][1] = tmp[1];
            bh2[np * 2 + 1][0] = tmp[2]; bh2[np * 2 + 1][1] = tmp[3];
            ldsm4(tmp, sb + 49152 + off);
            bl2[np * 2][0] = tmp[0]; bl2[np * 2][1] = tmp[1];
            bl2[np * 2 + 1][0] = tmp[2]; bl2[np * 2 + 1][1] = tmp[3];
        }
#pragma unroll
        for (int m = 0; m < 2; m++)
#pragma unroll
            for (int n = 0; n < 8; n++) {
                mma16816(c[m][n], ah[m], bh2[n]);
                mma16816(c[m][n], ah[m], bl2[n]);
                mma16816(c[m][n], al[m], bh2[n]);
            }
    }

    __syncthreads();

    float* Es = (float*)SB;    // [128][132]
    const int g4 = lane >> 2, l4 = lane & 3;
#pragma unroll
    for (int m = 0; m < 2; m++)
#pragma unroll
        for (int n = 0; n < 8; n++) {
            const int rm = wm * 32 + m * 16 + g4;
            const int cn = wn * 64 + n * 8 + l4 * 2;
            const float f0 = fmask[cn], f1 = fmask[cn + 1];
            float2 e01, e23;
            e01.x = __expf(c[m][n][0] * 0.125f) * f0;
            e01.y = __expf(c[m][n][1] * 0.125f) * f1;
            e23.x = __expf(c[m][n][2] * 0.125f) * f0;
            e23.y = __expf(c[m][n][3] * 0.125f) * f1;
            *(float2*)&Es[rm * 132 + cn] = e01;
            *(float2*)&Es[(rm + 8) * 132 + cn] = e23;
        }
    __syncthreads();

#pragma unroll
    for (int pass = 0; pass < 16; pass++) {
        const int row = w + pass * 8;
        const float4 v = *(const float4*)&Es[row * 132 + lane * 4];
        float rs = (v.x + v.y) + (v.z + v.w);
#pragma unroll
        for (int o = 16; o > 0; o >>= 1)
            rs += __shfl_xor_sync(0xffffffffu, rs, o);
        *(float4*)&attn[((size_t)(bh * S_DIM + s0 + row)) * S_DIM + t0 + lane * 4] = v;
        if (lane == 0)
            g_part[((blockIdx.x * NBH + bh) << 10) + s0 + row] = rs;
    }
}

// ---------------------------------------------------------------------------
// pv_mma_kernel: per (t-tile 128, bh). Full s-loop, 32 chunks of 32.
// smem layout (bytes):
//   [0, 32768)      Ef[2][32][128] f32  (raw E double buffer)
//   [32768, 41472)  Ebh[32][136] bf16
//   [41472, 50176)  Ebl[32][136] bf16
//   [50176, 55296)  Vsh[64][40] bf16
//   [55296, 60416)  Vsl[64][40] bf16
//   [60416, 64512)  invs[1024] f32
// total = 64512 (R9 bug: was declared 63744 -> smem OOB on invs writes)
// epilogue Cs[128][66] f32 aliases base.
// ---------------------------------------------------------------------------
#define PV_DSMEM 64512

__global__ __launch_bounds__(256, 2) void pv_mma_kernel(
    const float* __restrict__ V, float* __restrict__ attn,
    float* __restrict__ ctx)
{
    extern __shared__ char smem_raw[];
    float* Ef = (float*)smem_raw;                                   // [2][32][128]
    __nv_bfloat16* Ebh = (__nv_bfloat16*)(smem_raw + 32768);        // [32][136]
    __nv_bfloat16* Ebl = (__nv_bfloat16*)(smem_raw + 41472);
    __nv_bfloat16* Vsh = (__nv_bfloat16*)(smem_raw + 50176);        // [64][40]
    __nv_bfloat16* Vsl = (__nv_bfloat16*)(smem_raw + 55296);
    float* invs = (float*)(smem_raw + 60416);                        // [1024]
    float* Cs = (float*)smem_raw;                                    // alias [128][66]

    const uint32_t uEbh = s2u(Ebh), uEbl = s2u(Ebl);
    const uint32_t uVsh = s2u(Vsh), uVsl = s2u(Vsl);

    const int bh = blockIdx.y;
    const int t0 = blockIdx.x * 128;
    const int b = bh / H_NUM;
    const int h = bh - b * H_NUM;
    const float* Vb = V + (size_t)bh * D_DIM * S_DIM;
    float* Ab = attn + (size_t)bh * S_DIM * S_DIM;

    const int tid = threadIdx.x;
    const int w = tid >> 5, lane = tid & 31;
    const int wm = w & 3, wn = w >> 2;
    const int q8 = lane >> 3, r8 = lane & 7;
    const int g4 = lane >> 2, l4 = lane & 3;
    const int cs = tid >> 3, cq = tid & 7;     // E convert map: row s, t-quarter
    const int vd = tid >> 2, vc = tid & 3;     // V map: d row, s-octet

    // E fp32 tile cp.async: 1024 16B-chunks, 4/thread
#define PV_CPE(ci, buf)                                                        \
    {                                                                          \
        _Pragma("unroll")                                                      \
        for (int u = 0; u < 4; u++) {                                          \
            const int id = tid + u * 256;                                      \
            const int row = id >> 5;                                           \
            const int cc4 = (id & 31) * 4;                                     \
            asm volatile("cp.async.cg.shared.global [%0], [%1], 16;" ::        \
                "r"(s2u(&Ef[(buf) * 4096 + row * 128 + cc4])),                 \
                "l"(&Ab[(size_t)((ci) * 32 + row) * S_DIM + t0 + cc4]));       \
        }                                                                      \
        asm volatile("cp.async.commit_group;");                                \
    }

    float4 vr0, vr1;   // V prefetch regs: V[vd][ci*32 + vc*8 .. +7]
#define PV_LDGV(ci)                                                            \
    {                                                                          \
        const float* vp = &Vb[(size_t)vd * S_DIM + (ci) * 32 + vc * 8];        \
        vr0 = *(const float4*)(vp + 0);                                        \
        vr1 = *(const float4*)(vp + 4);                                        \
    }

    // convert chunk cc from Ef[buf]: attn STG + E hi/lo STS + V hi/lo STS
#define PV_CONVERT(cc, buf)                                                    \
    {                                                                          \
        const float iv = invs[(cc) * 32 + cs];                                 \
        float e[16];                                                           \
        _Pragma("unroll")                                                      \
        for (int i = 0; i < 4; i++) {                                          \
            const float4 e4 = *(const float4*)&Ef[(buf) * 4096 + cs * 128 + cq * 16 + i * 4]; \
            e[i * 4 + 0] = e4.x; e[i * 4 + 1] = e4.y;                          \
            e[i * 4 + 2] = e4.z; e[i * 4 + 3] = e4.w;                          \
            float4 a4;                                                         \
            a4.x = e4.x * iv; a4.y = e4.y * iv;                                \
            a4.z = e4.z * iv; a4.w = e4.w * iv;                                \
            *(float4*)&Ab[(size_t)((cc) * 32 + cs) * S_DIM + t0 + cq * 16 + i * 4] = a4; \
        }                                                                      \
        __align__(16) __nv_bfloat16 hb[16], lb[16];                            \
        _Pragma("unroll")                                                      \
        for (int i = 0; i < 16; i++) {                                         \
            const __nv_bfloat16 hh = __float2bfloat16_rn(e[i]);                \
            hb[i] = hh;                                                        \
            lb[i] = __float2bfloat16_rn(e[i] - __bfloat162float(hh));          \
        }                                                                      \
        *(uint4*)&Ebh[cs * 136 + cq * 16 + 0] = *(const uint4*)&hb[0];         \
        *(uint4*)&Ebh[cs * 136 + cq * 16 + 8] = *(const uint4*)&hb[8];         \
        *(uint4*)&Ebl[cs * 136 + cq * 16 + 0] = *(const uint4*)&lb[0];         \
        *(uint4*)&Ebl[cs * 136 + cq * 16 + 8] = *(const uint4*)&lb[8];         \
        const float4 vi0 = *(const float4*)&invs[(cc) * 32 + vc * 8];          \
        const float4 vi1 = *(const float4*)&invs[(cc) * 32 + vc * 8 + 4];      \
        float p[8];                                                            \
        p[0] = vr0.x * vi0.x; p[1] = vr0.y * vi0.y;                            \
        p[2] = vr0.z * vi0.z; p[3] = vr0.w * vi0.w;                            \
        p[4] = vr1.x * vi1.x; p[5] = vr1.y * vi1.y;                            \
        p[6] = vr1.z * vi1.z; p[7] = vr1.w * vi1.w;                            \
        __align__(16) __nv_bfloat16 vh[8], vl[8];                              \
        _Pragma("unroll")                                                      \
        for (int i = 0; i < 8; i++) {                                          \
            const __nv_bfloat16 hh = __float2bfloat16_rn(p[i]);                \
            vh[i] = hh;                                                        \
            vl[i] = __float2bfloat16_rn(p[i] - __bfloat162float(hh));          \
        }                                                                      \
        *(uint4*)&Vsh[vd * 40 + vc * 8] = *(const uint4*)&vh[0];               \
        *(uint4*)&Vsl[vd * 40 + vc * 8] = *(const uint4*)&vl[0];               \
    }

    // ---- prologue ----
    PV_CPE(0, 0);
    PV_CPE(1, 1);
    PV_LDGV(0);
#pragma unroll
    for (int j = 0; j < 4; j++) {
        const int s = tid + j * 256;
        float sum = 0.f;
#pragma unroll
        for (int tb = 0; tb < 8; tb++)
            sum += g_part[((tb * NBH + bh) << 10) + s];
        invs[s] = 1.0f / sum;
    }
    asm volatile("cp.async.wait_group %0;" :: "n"(1));
    __syncthreads();
    PV_CONVERT(0, 0);
    PV_LDGV(1);
    __syncthreads();

    float c[8][4];
#pragma unroll
    for (int n = 0; n < 8; n++)
#pragma unroll
        for (int i = 0; i < 4; i++) c[n][i] = 0.f;

    for (int ci = 0; ci < 32; ci++) {
        // ---- MMA on chunk ci (Ebh/Ebl/Vsh/Vsl) ----
#pragma unroll
        for (int ks = 0; ks < 2; ks++) {
            uint32_t ah[4], al[4];
            const uint32_t aoff =
                (uint32_t)(wm * 16 + ((q8 & 1) << 3) + r8) * 80 + ks * 32 + (q8 >> 1) * 16;
            ldsm4(ah, uVsh + aoff);
            ldsm4(al, uVsl + aoff);
            uint32_t bhf[8][2], blf[8][2];
#pragma unroll
            for (int tp = 0; tp < 4; tp++) {
                const uint32_t boff =
                    (uint32_t)(ks * 16 + ((q8 & 1) << 3) + r8) * 272
                    + (wn * 64 + tp * 16) * 2 + (q8 >> 1) * 16;
                uint32_t tmp[4];
                ldsm4t(tmp, uEbh + boff);
                bhf[tp * 2][0] = tmp[0]; bhf[tp * 2][1] = tmp[1];
                bhf[tp * 2 + 1][0] = tmp[2]; bhf[tp * 2 + 1][1] = tmp[3];
                ldsm4t(tmp, uEbl + boff);
                blf[tp * 2][0] = tmp[0]; blf[tp * 2][1] = tmp[1];
                blf[tp * 2 + 1][0] = tmp[2]; blf[tp * 2 + 1][1] = tmp[3];
            }
#pragma unroll
            for (int n = 0; n < 8; n++) {
                mma16816(c[n], ah, bhf[n]);
                mma16816(c[n], ah, blf[n]);
                mma16816(c[n], al, bhf[n]);
            }
        }
        if (ci == 31) break;
        // ---- stage next chunk ----
        if (ci + 2 <= 31) {
            PV_CPE(ci + 2, ci & 1);
            asm volatile("cp.async.wait_group %0;" :: "n"(1));
        } else {
            asm volatile("cp.async.wait_group %0;" :: "n"(0));
        }
        __syncthreads();   // mma done reading Eb/Vs + Ef[(ci+1)&1] visible
        PV_CONVERT(ci + 1, (ci + 1) & 1);
        if (ci + 2 <= 31) PV_LDGV(ci + 2);
        __syncthreads();   // Eb/Vs ready
    }

    // ---- epilogue: stage ctx tile [t 128][d 64] and store ----
    __syncthreads();
#pragma unroll
    for (int n = 0; n < 8; n++) {
        const int tb = wn * 64 + n * 8 + l4 * 2;
        const int d0 = wm * 16 + g4;
        Cs[tb * 66 + d0]           = c[n][0];
        Cs[(tb + 1) * 66 + d0]     = c[n][1];
        Cs[tb * 66 + d0 + 8]       = c[n][2];
        Cs[(tb + 1) * 66 + d0 + 8] = c[n][3];
    }
    __syncthreads();
#pragma unroll
    for (int rr = 0; rr < 16; rr++) {
        const int t = w * 16 + rr;
        const float2 v = *(const float2*)&Cs[t * 66 + lane * 2];
        *(float2*)&ctx[((size_t)b * S_DIM + t0 + t) * (H_NUM * D_DIM)
                       + h * D_DIM + lane * 2] = v;
    }
}

// ---------------------------------------------------------------------------
extern "C" void kernel_launch(void* const* d_in, const int* in_sizes, int n_in,
                              void* d_out, int out_size)
{
    (void)in_sizes; (void)n_in; (void)out_size;
    const float* Q = (const float*)d_in[0];
    const float* K = (const float*)d_in[1];
    const float* V = (const float*)d_in[2];
    const int* mask = (const int*)d_in[3];

    float* ctx  = (float*)d_out;                 // (B, S, H*D)
    float* attn = ctx + CTX_ELEMS;               // (B, H, S, S)

    static int attr_set = 0;
    if (!attr_set) {
        cudaFuncSetAttribute(qk_mma_kernel, cudaFuncAttributeMaxDynamicSharedMemorySize,
                             QK_DSMEM);
        cudaFuncSetAttribute(pv_mma_kernel, cudaFuncAttributeMaxDynamicSharedMemorySize,
                             PV_DSMEM);
        attr_set = 1;
    }

    convert_kernel<<<dim3(16, NBH, 2), 256>>>(K, Q);
    qk_mma_kernel<<<dim3(8, 8, NBH), 256, QK_DSMEM>>>(mask, attn);
    pv_mma_kernel<<<dim3(8, NBH), 256, PV_DSMEM>>>(V, attn, ctx);
}

// round 12
// speedup vs baseline: 1.9678x; 1.0860x over previous
#include <cuda_runtime.h>
#include <cuda_bf16.h>
#include <cstdint>

// Shapes (fixed): B=8, H=12, D=64, S=1024
// scores[b,h,s,t] = (1/8) * sum_d K[b,h,d,s] * Q[b,h,d,t]
// mask over t (per b), softmax over t, context[b,h,d,t] = sum_s V[b,h,d,s]*attn[b,h,s,t]
// out = concat( context as (B,S,H*D), attn as (B,H,S,S) )
//
// convert_kernel : K,Q fp32 [bh][d][s] -> bf16 hi/lo planes [bh][s][d].
// qk_mma_kernel  : mma.sync bf16-split QK GEMM; epilogue writes E = exp*mask
//                  as bf16 hi/lo planes (g_Ehi/g_Elo) + row sums (g_part).
// vsplit_kernel  : inv[s] = 1/rowsum; writes inv*V as bf16 hi/lo planes.
// pv_mma_kernel  : pure 3-pass MMA from precomputed planes; writes normalized
//                  attn = (Ehi+Elo)*inv and ctx. No conversions inside.

#define D_DIM 64
#define S_DIM 1024
#define H_NUM 12
#define B_NUM 8
#define NBH   (B_NUM * H_NUM)
#define CTX_ELEMS ((size_t)B_NUM * S_DIM * H_NUM * D_DIM)   // 6291456
#define PLANE_ELEMS (NBH * S_DIM * D_DIM)                    // 6291456

__device__ __forceinline__ unsigned s2u(const void* p) {
    return (unsigned)__cvta_generic_to_shared(p);
}
__device__ __forceinline__ uint32_t swz128(uint32_t off) {
    return off ^ ((off >> 3) & 0x70);
}
__device__ __forceinline__ void ldsm4(uint32_t* r, uint32_t addr) {
    asm volatile("ldmatrix.sync.aligned.m8n8.x4.shared.b16 {%0,%1,%2,%3}, [%4];"
                 : "=r"(r[0]), "=r"(r[1]), "=r"(r[2]), "=r"(r[3]) : "r"(addr));
}
__device__ __forceinline__ void ldsm4t(uint32_t* r, uint32_t addr) {
    asm volatile("ldmatrix.sync.aligned.m8n8.x4.trans.shared.b16 {%0,%1,%2,%3}, [%4];"
                 : "=r"(r[0]), "=r"(r[1]), "=r"(r[2]), "=r"(r[3]) : "r"(addr));
}
__device__ __forceinline__ void mma16816(float* c, const uint32_t* a, const uint32_t* b) {
    asm volatile(
        "mma.sync.aligned.m16n8k16.row.col.f32.bf16.bf16.f32 "
        "{%0,%1,%2,%3}, {%4,%5,%6,%7}, {%8,%9}, {%0,%1,%2,%3};"
        : "+f"(c[0]), "+f"(c[1]), "+f"(c[2]), "+f"(c[3])
        : "r"(a[0]), "r"(a[1]), "r"(a[2]), "r"(a[3]), "r"(b[0]), "r"(b[1]));
}
// pack two floats to bf16x2: low 16 bits = lo arg, high = hi arg
__device__ __forceinline__ uint32_t cvt2(float lo, float hi) {
    uint32_t r;
    asm("cvt.rn.bf16x2.f32 %0, %1, %2;" : "=r"(r) : "f"(hi), "f"(lo));
    return r;
}
#define CP16(dst_u, src_p) \
    asm volatile("cp.async.cg.shared.global [%0], [%1], 16;" :: "r"(dst_u), "l"(src_p))

// ---------------- global scratch ----------------
// planes: 0=K_hi 1=K_lo 2=Q_hi 3=Q_lo, each [bh][s][d] bf16
__device__ __nv_bfloat16 g_cvt[4 * PLANE_ELEMS];
// Partial row sums: [t_block(8)][bh(96)][s(1024)]
__device__ float g_part[8 * NBH * S_DIM];
// E hi/lo planes: [bh][s][t] bf16 (unnormalized exp, masked)
__device__ __nv_bfloat16 g_Ehi[(size_t)NBH * S_DIM * S_DIM];
__device__ __nv_bfloat16 g_Elo[(size_t)NBH * S_DIM * S_DIM];
// inv*V hi/lo planes: [bh][d][s] bf16
__device__ __nv_bfloat16 g_Vh[PLANE_ELEMS];
__device__ __nv_bfloat16 g_Vl[PLANE_ELEMS];

// ---------------------------------------------------------------------------
// convert_kernel (unchanged)
// ---------------------------------------------------------------------------
__global__ __launch_bounds__(256) void convert_kernel(
    const float* __restrict__ K, const float* __restrict__ Q)
{
    const int z = blockIdx.z;
    const int bh = blockIdx.y;
    const int s0 = blockIdx.x * 64;
    const float* X = z ? Q : K;
    __nv_bfloat16* hiP = g_cvt + (size_t)(z * 2) * PLANE_ELEMS;
    __nv_bfloat16* loP = g_cvt + (size_t)(z * 2 + 1) * PLANE_ELEMS;

    __shared__ float t[64][68];
    const int tid = threadIdx.x;

#pragma unroll
    for (int j = 0; j < 4; j++) {
        const int d = (tid >> 4) + j * 16;
        const int s = (tid & 15) * 4;
        const float4 v = *(const float4*)&X[(((size_t)bh * 64 + d) << 10) + s0 + s];
        t[d][s + 0] = v.x; t[d][s + 1] = v.y; t[d][s + 2] = v.z; t[d][s + 3] = v.w;
    }
    __syncthreads();

    const int sl = tid >> 2;
    const int dq = (tid & 3) * 16;
    __align__(16) __nv_bfloat16 hb[16], lb[16];
#pragma unroll
    for (int q = 0; q < 16; q++) {
        const float x = t[dq + q][sl];
        const __nv_bfloat16 h = __float2bfloat16_rn(x);
        hb[q] = h;
        lb[q] = __float2bfloat16_rn(x - __bfloat162float(h));
    }
    const size_t o = ((size_t)bh * S_DIM + s0 + sl) * D_DIM + dq;
    *(uint4*)&hiP[o]     = *(const uint4*)&hb[0];
    *(uint4*)&hiP[o + 8] = *(const uint4*)&hb[8];
    *(uint4*)&loP[o]     = *(const uint4*)&lb[0];
    *(uint4*)&loP[o + 8] = *(const uint4*)&lb[8];
}

// ---------------------------------------------------------------------------
// qk_mma_kernel: as R8/R11 but epilogue stores E as bf16 hi/lo planes.
// ---------------------------------------------------------------------------
#define QK_DSMEM (1024 + 68096)

__global__ __launch_bounds__(256) void qk_mma_kernel(const int* __restrict__ mask)
{
    extern __shared__ char raw[];
    char* SB = (char*)(((uintptr_t)raw + 1023) & ~(uintptr_t)1023);
    const uint32_t sb = s2u(SB);
    float* fmask = (float*)(SB + 67584);

    const int bh = blockIdx.z;
    const int s0 = blockIdx.y * 128;
    const int t0 = blockIdx.x * 128;
    const int b = bh / H_NUM;
    const int tid = threadIdx.x;
    const int w = tid >> 5, lane = tid & 31;
    const int wm = w & 3, wn = w >> 2;

#pragma unroll
    for (int u = 0; u < 16; u++) {
        const int id = tid + u * 256;
        const int T = id >> 10;
        const int r = (id >> 3) & 127;
        const int c = id & 7;
        const int row0 = (T >= 2) ? t0 : s0;
        const __nv_bfloat16* src = g_cvt + (size_t)T * PLANE_ELEMS
            + ((size_t)bh * S_DIM + row0 + r) * D_DIM + c * 8;
        const uint32_t dst = sb + T * 16384 + swz128(r * 128 + c * 16);
        CP16(dst, src);
    }
    asm volatile("cp.async.commit_group;");

    if (tid < 128) fmask[tid] = mask[b * S_DIM + t0 + tid] ? 1.0f : 0.0f;

    asm volatile("cp.async.wait_group 0;");
    __syncthreads();

    float c[2][8][4];
#pragma unroll
    for (int m = 0; m < 2; m++)
#pragma unroll
        for (int n = 0; n < 8; n++)
#pragma unroll
            for (int i = 0; i < 4; i++) c[m][n][i] = 0.f;

    const int q8 = lane >> 3, r8 = lane & 7;

#pragma unroll
    for (int ks = 0; ks < 4; ks++) {
        uint32_t ah[2][4], al[2][4], bh2[8][2], bl2[8][2];
#pragma unroll
        for (int m = 0; m < 2; m++) {
            const int rowA = wm * 32 + m * 16 + ((q8 & 1) << 3) + r8;
            const uint32_t off = swz128(rowA * 128 + (2 * ks + (q8 >> 1)) * 16);
            ldsm4(ah[m], sb + off);
            ldsm4(al[m], sb + 16384 + off);
        }
#pragma unroll
        for (int np = 0; np < 4; np++) {
            const int rowB = wn * 64 + np * 16 + ((q8 >> 1) << 3) + r8;
            const uint32_t off = swz128(rowB * 128 + (2 * ks + (q8 & 1)) * 16);
            uint32_t tmp[4];
            ldsm4(tmp, sb + 32768 + off);
            bh2[np * 2][0] = tmp[0]; bh2[np * 2][1] = tmp[1];
            bh2[np * 2 + 1][0] = tmp[2]; bh2[np * 2 + 1][1] = tmp[3];
            ldsm4(tmp, sb + 49152 + off);
            bl2[np * 2][0] = tmp[0]; bl2[np * 2][1] = tmp[1];
            bl2[np * 2 + 1][0] = tmp[2]; bl2[np * 2 + 1][1] = tmp[3];
        }
#pragma unroll
        for (int m = 0; m < 2; m++)
#pragma unroll
            for (int n = 0; n < 8; n++) {
                mma16816(c[m][n], ah[m], bh2[n]);
                mma16816(c[m][n], ah[m], bl2[n]);
                mma16816(c[m][n], al[m], bh2[n]);
            }
    }

    __syncthreads();

    float* Es = (float*)SB;    // [128][132]
    const int g4 = lane >> 2, l4 = lane & 3;
#pragma unroll
    for (int m = 0; m < 2; m++)
#pragma unroll
        for (int n = 0; n < 8; n++) {
            const int rm = wm * 32 + m * 16 + g4;
            const int cn = wn * 64 + n * 8 + l4 * 2;
            const float f0 = fmask[cn], f1 = fmask[cn + 1];
            float2 e01, e23;
            e01.x = __expf(c[m][n][0] * 0.125f) * f0;
            e01.y = __expf(c[m][n][1] * 0.125f) * f1;
            e23.x = __expf(c[m][n][2] * 0.125f) * f0;
            e23.y = __expf(c[m][n][3] * 0.125f) * f1;
            *(float2*)&Es[rm * 132 + cn] = e01;
            *(float2*)&Es[(rm + 8) * 132 + cn] = e23;
        }
    __syncthreads();

    // store E as bf16 hi/lo planes + row sums; one row per warp per pass
#pragma unroll
    for (int pass = 0; pass < 16; pass++) {
        const int row = w + pass * 8;
        const float4 v = *(const float4*)&Es[row * 132 + lane * 4];
        float rs = (v.x + v.y) + (v.z + v.w);
#pragma unroll
        for (int o = 16; o > 0; o >>= 1)
            rs += __shfl_xor_sync(0xffffffffu, rs, o);
        if (lane == 0)
            g_part[((blockIdx.x * NBH + bh) << 10) + s0 + row] = rs;

        const uint32_t h01 = cvt2(v.x, v.y);
        const uint32_t h23 = cvt2(v.z, v.w);
        const float hx = __uint_as_float(h01 << 16);
        const float hy = __uint_as_float(h01 & 0xFFFF0000u);
        const float hz = __uint_as_float(h23 << 16);
        const float hw = __uint_as_float(h23 & 0xFFFF0000u);
        const uint32_t l01 = cvt2(v.x - hx, v.y - hy);
        const uint32_t l23 = cvt2(v.z - hz, v.w - hw);
        const size_t ei = ((size_t)(bh * S_DIM + s0 + row)) * S_DIM + t0 + lane * 4;
        *(uint2*)&g_Ehi[ei] = make_uint2(h01, h23);
        *(uint2*)&g_Elo[ei] = make_uint2(l01, l23);
    }
}

// ---------------------------------------------------------------------------
// vsplit_kernel: inv[s] from g_part; writes inv*V as bf16 hi/lo planes
// [bh][d][s]. grid (4 s-quarters, 96 bh), 256 threads.
// ---------------------------------------------------------------------------
__global__ __launch_bounds__(256) void vsplit_kernel(const float* __restrict__ V)
{
    __shared__ float inv[256];
    const int bh = blockIdx.y;
    const int q = blockIdx.x;
    const int tid = threadIdx.x;
    {
        float sum = 0.f;
#pragma unroll
        for (int tb = 0; tb < 8; tb++)
            sum += g_part[((tb * NBH + bh) << 10) + q * 256 + tid];
        inv[tid] = 1.0f / sum;
    }
    __syncthreads();

    const float* Vb = V + (size_t)bh * D_DIM * S_DIM + q * 256;
    __nv_bfloat16* Hh = g_Vh + (size_t)bh * D_DIM * S_DIM + q * 256;
    __nv_bfloat16* Hl = g_Vl + (size_t)bh * D_DIM * S_DIM + q * 256;

#pragma unroll
    for (int u = 0; u < 16; u++) {
        const int f = tid + u * 256;         // float4 index in [64 d][64 f4]
        const int dr = f >> 6;
        const int c4 = (f & 63) * 4;
        float4 v = *(const float4*)&Vb[(size_t)dr * S_DIM + c4];
        const float4 iv = *(const float4*)&inv[c4];
        v.x *= iv.x; v.y *= iv.y; v.z *= iv.z; v.w *= iv.w;
        const uint32_t h01 = cvt2(v.x, v.y);
        const uint32_t h23 = cvt2(v.z, v.w);
        const float hx = __uint_as_float(h01 << 16);
        const float hy = __uint_as_float(h01 & 0xFFFF0000u);
        const float hz = __uint_as_float(h23 << 16);
        const float hw = __uint_as_float(h23 & 0xFFFF0000u);
        const uint32_t l01 = cvt2(v.x - hx, v.y - hy);
        const uint32_t l23 = cvt2(v.z - hz, v.w - hw);
        *(uint2*)&Hh[(size_t)dr * S_DIM + c4] = make_uint2(h01, h23);
        *(uint2*)&Hl[(size_t)dr * S_DIM + c4] = make_uint2(l01, l23);
    }
}

// ---------------------------------------------------------------------------
// pv_mma_kernel: per (t-tile 128, bh). 32 s-chunks of 32; all operands
// precomputed bf16 planes, double-buffered via cp.async. Writes attn =
// (Ehi+Elo)*inv and ctx. Fragment math identical to validated R11 kernel.
// smem: [0,17408)  Ehi[2][32][136]b | [17408,34816) Elo
//       [34816,45056) Vh[2][64][40]b | [45056,55296) Vl
//       [55296,59392) invs[1024] f32        total 59392
// epilogue Cs[128][66] f32 aliases base (33792 B).
// ---------------------------------------------------------------------------
#define PV_DSMEM 59392

__global__ __launch_bounds__(256, 2) void pv_mma_kernel(
    float* __restrict__ attn, float* __restrict__ ctx)
{
    extern __shared__ char smem_raw[];
    const uint32_t uEh = s2u(smem_raw);
    const uint32_t uEl = uEh + 17408;
    const uint32_t uVh = uEh + 34816;
    const uint32_t uVl = uEh + 45056;
    float* invs = (float*)(smem_raw + 55296);
    float* Cs = (float*)smem_raw;

    const int bh = blockIdx.y;
    const int t0 = blockIdx.x * 128;
    const int b = bh / H_NUM;
    const int h = bh - b * H_NUM;
    const __nv_bfloat16* Ehg = g_Ehi + (size_t)bh * S_DIM * S_DIM;
    const __nv_bfloat16* Elg = g_Elo + (size_t)bh * S_DIM * S_DIM;
    const __nv_bfloat16* Vhg = g_Vh + (size_t)bh * D_DIM * S_DIM;
    const __nv_bfloat16* Vlg = g_Vl + (size_t)bh * D_DIM * S_DIM;
    float* Ab = attn + (size_t)bh * S_DIM * S_DIM;

    const int tid = threadIdx.x;
    const int w = tid >> 5, lane = tid & 31;
    const int wm = w & 3, wn = w >> 2;
    const int q8 = lane >> 3, r8 = lane & 7;
    const int g4 = lane >> 2, l4 = lane & 3;
    const int cs = tid >> 3, cq = tid & 7;      // writeback map
    const int vrow = tid >> 2, vc = tid & 3;    // V cp.async map

#define PV_CP(ci, buf)                                                         \
    {                                                                          \
        _Pragma("unroll")                                                      \
        for (int u = 0; u < 2; u++) {                                          \
            const int id = tid + u * 256;                                      \
            const int row = id >> 4;                                           \
            const int c16 = id & 15;                                           \
            const size_t gsrc = (size_t)((ci) * 32 + row) * S_DIM + t0 + c16 * 8; \
            const uint32_t dst = (uint32_t)(row * 272 + c16 * 16 + (buf) * 8704); \
            CP16(uEh + dst, Ehg + gsrc);                                       \
            CP16(uEl + dst, Elg + gsrc);                                       \
        }                                                                      \
        {                                                                      \
            const size_t gv = (size_t)vrow * S_DIM + (ci) * 32 + vc * 8;       \
            const uint32_t dv = (uint32_t)(vrow * 80 + vc * 16 + (buf) * 5120); \
            CP16(uVh + dv, Vhg + gv);                                          \
            CP16(uVl + dv, Vlg + gv);                                          \
        }                                                                      \
        asm volatile("cp.async.commit_group;");                                \
    }

    // ---- prologue ----
    PV_CP(0, 0);
    PV_CP(1, 1);
#pragma unroll
    for (int j = 0; j < 4; j++) {
        const int s = tid + j * 256;
        float sum = 0.f;
#pragma unroll
        for (int tb = 0; tb < 8; tb++)
            sum += g_part[((tb * NBH + bh) << 10) + s];
        invs[s] = 1.0f / sum;
    }
    asm volatile("cp.async.wait_group %0;" :: "n"(1));
    __syncthreads();

    float c[8][4];
#pragma unroll
    for (int n = 0; n < 8; n++)
#pragma unroll
        for (int i = 0; i < 4; i++) c[n][i] = 0.f;

    for (int ci = 0; ci < 32; ci++) {
        const int cur = ci & 1;
        // ---- MMA on chunk ci ----
#pragma unroll
        for (int ks = 0; ks < 2; ks++) {
            uint32_t ah[4], al[4];
            const uint32_t aoff =
                (uint32_t)(wm * 16 + ((q8 & 1) << 3) + r8) * 80 + ks * 32 + (q8 >> 1) * 16
                + cur * 5120;
            ldsm4(ah, uVh + aoff);
            ldsm4(al, uVl + aoff);
            uint32_t bhf[8][2], blf[8][2];
#pragma unroll
            for (int tp = 0; tp < 4; tp++) {
                const uint32_t boff =
                    (uint32_t)(ks * 16 + ((q8 & 1) << 3) + r8) * 272
                    + (wn * 64 + tp * 16) * 2 + (q8 >> 1) * 16 + cur * 8704;
                uint32_t tmp[4];
                ldsm4t(tmp, uEh + boff);
                bhf[tp * 2][0] = tmp[0]; bhf[tp * 2][1] = tmp[1];
                bhf[tp * 2 + 1][0] = tmp[2]; bhf[tp * 2 + 1][1] = tmp[3];
                ldsm4t(tmp, uEl + boff);
                blf[tp * 2][0] = tmp[0]; blf[tp * 2][1] = tmp[1];
                blf[tp * 2 + 1][0] = tmp[2]; blf[tp * 2 + 1][1] = tmp[3];
            }
#pragma unroll
            for (int n = 0; n < 8; n++) {
                mma16816(c[n], ah, bhf[n]);
                mma16816(c[n], ah, blf[n]);
                mma16816(c[n], al, bhf[n]);
            }
        }
        // ---- attn writeback for chunk ci: (hi+lo)*inv ----
        {
            const float iv = invs[ci * 32 + cs];
            const uint32_t sb2 = cur * 8704 + cs * 272 + cq * 32;
            const uint4 H0 = *(const uint4*)(smem_raw + sb2);
            const uint4 H1 = *(const uint4*)(smem_raw + sb2 + 16);
            const uint4 L0 = *(const uint4*)(smem_raw + 17408 + sb2);
            const uint4 L1 = *(const uint4*)(smem_raw + 17408 + sb2 + 16);
            const uint32_t hs[8] = {H0.x, H0.y, H0.z, H0.w, H1.x, H1.y, H1.z, H1.w};
            const uint32_t ls[8] = {L0.x, L0.y, L0.z, L0.w, L1.x, L1.y, L1.z, L1.w};
            float* op = &Ab[(size_t)(ci * 32 + cs) * S_DIM + t0 + cq * 16];
#pragma unroll
            for (int i = 0; i < 4; i++) {
                float4 a4;
                a4.x = (__uint_as_float(hs[2 * i] << 16)
                        + __uint_as_float(ls[2 * i] << 16)) * iv;
                a4.y = (__uint_as_float(hs[2 * i] & 0xFFFF0000u)
                        + __uint_as_float(ls[2 * i] & 0xFFFF0000u)) * iv;
                a4.z = (__uint_as_float(hs[2 * i + 1] << 16)
                        + __uint_as_float(ls[2 * i + 1] << 16)) * iv;
                a4.w = (__uint_as_float(hs[2 * i + 1] & 0xFFFF0000u)
                        + __uint_as_float(ls[2 * i + 1] & 0xFFFF0000u)) * iv;
                *(float4*)(op + i * 4) = a4;
            }
        }
        if (ci == 31) break;
        asm volatile("cp.async.wait_group %0;" :: "n"(0));
        __syncthreads();
        if (ci + 2 < 32) PV_CP(ci + 2, cur);
    }

    // ---- epilogue: stage ctx tile [t 128][d 64] and store ----
    __syncthreads();
#pragma unroll
    for (int n = 0; n < 8; n++) {
        const int tb = wn * 64 + n * 8 + l4 * 2;
        const int d0 = wm * 16 + g4;
        Cs[tb * 66 + d0]           = c[n][0];
        Cs[(tb + 1) * 66 + d0]     = c[n][1];
        Cs[tb * 66 + d0 + 8]       = c[n][2];
        Cs[(tb + 1) * 66 + d0 + 8] = c[n][3];
    }
    __syncthreads();
#pragma unroll
    for (int rr = 0; rr < 16; rr++) {
        const int t = w * 16 + rr;
        const float2 v = *(const float2*)&Cs[t * 66 + lane * 2];
        *(float2*)&ctx[((size_t)b * S_DIM + t0 + t) * (H_NUM * D_DIM)
                       + h * D_DIM + lane * 2] = v;
    }
}

// ---------------------------------------------------------------------------
extern "C" void kernel_launch(void* const* d_in, const int* in_sizes, int n_in,
                              void* d_out, int out_size)
{
    (void)in_sizes; (void)n_in; (void)out_size;
    const float* Q = (const float*)d_in[0];
    const float* K = (const float*)d_in[1];
    const float* V = (const float*)d_in[2];
    const int* mask = (const int*)d_in[3];

    float* ctx  = (float*)d_out;                 // (B, S, H*D)
    float* attn = ctx + CTX_ELEMS;               // (B, H, S, S)

    static int attr_set = 0;
    if (!attr_set) {
        cudaFuncSetAttribute(qk_mma_kernel, cudaFuncAttributeMaxDynamicSharedMemorySize,
                             QK_DSMEM);
        cudaFuncSetAttribute(pv_mma_kernel, cudaFuncAttributeMaxDynamicSharedMemorySize,
                             PV_DSMEM);
        attr_set = 1;
    }

    convert_kernel<<<dim3(16, NBH, 2), 256>>>(K, Q);
    qk_mma_kernel<<<dim3(8, 8, NBH), 256, QK_DSMEM>>>(mask);
    vsplit_kernel<<<dim3(4, NBH), 256>>>(V);
    pv_mma_kernel<<<dim3(8, NBH), 256, PV_DSMEM>>>(attn, ctx);
}

// round 13
// speedup vs baseline: 2.1523x; 1.0938x over previous
#include <cuda_runtime.h>
#include <cuda_bf16.h>
#include <cstdint>

// Shapes (fixed): B=8, H=12, D=64, S=1024
// scores[b,h,s,t] = (1/8) * sum_d K[b,h,d,s] * Q[b,h,d,t]
// mask over t (per b), softmax over t, context[b,h,d,t] = sum_s V[b,h,d,s]*attn[b,h,s,t]
// out = concat( context as (B,S,H*D), attn as (B,H,S,S) )
//
// convert_kernel : K,Q fp32 [bh][d][s] -> bf16 hi/lo planes [bh][s][d].
// rows_kernel    : per (s-tile, bh): QK MMA over all t (8 blocks), exp*mask,
//                  row sums only -> g_part slots 0,1. NO E stored.
// vsplit_kernel  : inv = 1/(slot0+slot1); writes inv*V bf16 hi/lo planes + g_inv.
// pv2_kernel     : per (t-tile, bh): per 32-s chunk RECOMPUTES E via QK MMA,
//                  exp -> bf16 hi/lo smem, then PV MMA (3-pass) + attn write.

#define D_DIM 64
#define S_DIM 1024
#define H_NUM 12
#define B_NUM 8
#define NBH   (B_NUM * H_NUM)
#define CTX_ELEMS ((size_t)B_NUM * S_DIM * H_NUM * D_DIM)   // 6291456
#define PLANE_ELEMS (NBH * S_DIM * D_DIM)                    // 6291456

__device__ __forceinline__ unsigned s2u(const void* p) {
    return (unsigned)__cvta_generic_to_shared(p);
}
__device__ __forceinline__ uint32_t swz128(uint32_t off) {
    return off ^ ((off >> 3) & 0x70);
}
__device__ __forceinline__ void ldsm4(uint32_t* r, uint32_t addr) {
    asm volatile("ldmatrix.sync.aligned.m8n8.x4.shared.b16 {%0,%1,%2,%3}, [%4];"
                 : "=r"(r[0]), "=r"(r[1]), "=r"(r[2]), "=r"(r[3]) : "r"(addr));
}
__device__ __forceinline__ void ldsm4t(uint32_t* r, uint32_t addr) {
    asm volatile("ldmatrix.sync.aligned.m8n8.x4.trans.shared.b16 {%0,%1,%2,%3}, [%4];"
                 : "=r"(r[0]), "=r"(r[1]), "=r"(r[2]), "=r"(r[3]) : "r"(addr));
}
__device__ __forceinline__ void mma16816(float* c, const uint32_t* a, const uint32_t* b) {
    asm volatile(
        "mma.sync.aligned.m16n8k16.row.col.f32.bf16.bf16.f32 "
        "{%0,%1,%2,%3}, {%4,%5,%6,%7}, {%8,%9}, {%0,%1,%2,%3};"
        : "+f"(c[0]), "+f"(c[1]), "+f"(c[2]), "+f"(c[3])
        : "r"(a[0]), "r"(a[1]), "r"(a[2]), "r"(a[3]), "r"(b[0]), "r"(b[1]));
}
// pack two floats to bf16x2 (low 16 = first arg)
__device__ __forceinline__ uint32_t cvt2(float lo, float hi) {
    uint32_t r;
    asm("cvt.rn.bf16x2.f32 %0, %1, %2;" : "=r"(r) : "f"(hi), "f"(lo));
    return r;
}
#define CP16(dst_u, src_p) \
    asm volatile("cp.async.cg.shared.global [%0], [%1], 16;" :: "r"(dst_u), "l"(src_p))
#define CP_COMMIT() asm volatile("cp.async.commit_group;")

// ---------------- global scratch ----------------
// planes: 0=K_hi 1=K_lo 2=Q_hi 3=Q_lo, each [bh][s][d] bf16
__device__ __nv_bfloat16 g_cvt[4 * PLANE_ELEMS];
// Partial row sums: [slot(2)][bh(96)][s(1024)] (slots 0,1 = wn halves)
__device__ float g_part[8 * NBH * S_DIM];
// inv*V hi/lo planes: [bh][d][s] bf16
__device__ __nv_bfloat16 g_Vh[PLANE_ELEMS];
__device__ __nv_bfloat16 g_Vl[PLANE_ELEMS];
// inverse row sums: [bh][s]
__device__ float g_inv[NBH * S_DIM];

// ---------------------------------------------------------------------------
// convert_kernel (unchanged)
// ---------------------------------------------------------------------------
__global__ __launch_bounds__(256) void convert_kernel(
    const float* __restrict__ K, const float* __restrict__ Q)
{
    const int z = blockIdx.z;
    const int bh = blockIdx.y;
    const int s0 = blockIdx.x * 64;
    const float* X = z ? Q : K;
    __nv_bfloat16* hiP = g_cvt + (size_t)(z * 2) * PLANE_ELEMS;
    __nv_bfloat16* loP = g_cvt + (size_t)(z * 2 + 1) * PLANE_ELEMS;

    __shared__ float t[64][68];
    const int tid = threadIdx.x;

#pragma unroll
    for (int j = 0; j < 4; j++) {
        const int d = (tid >> 4) + j * 16;
        const int s = (tid & 15) * 4;
        const float4 v = *(const float4*)&X[(((size_t)bh * 64 + d) << 10) + s0 + s];
        t[d][s + 0] = v.x; t[d][s + 1] = v.y; t[d][s + 2] = v.z; t[d][s + 3] = v.w;
    }
    __syncthreads();

    const int sl = tid >> 2;
    const int dq = (tid & 3) * 16;
    __align__(16) __nv_bfloat16 hb[16], lb[16];
#pragma unroll
    for (int q = 0; q < 16; q++) {
        const float x = t[dq + q][sl];
        const __nv_bfloat16 h = __float2bfloat16_rn(x);
        hb[q] = h;
        lb[q] = __float2bfloat16_rn(x - __bfloat162float(h));
    }
    const size_t o = ((size_t)bh * S_DIM + s0 + sl) * D_DIM + dq;
    *(uint4*)&hiP[o]     = *(const uint4*)&hb[0];
    *(uint4*)&hiP[o + 8] = *(const uint4*)&hb[8];
    *(uint4*)&loP[o]     = *(const uint4*)&lb[0];
    *(uint4*)&loP[o + 8] = *(const uint4*)&lb[8];
}

// ---------------------------------------------------------------------------
// rows_kernel: per (s-tile 128, bh). K tile staged once; loop 8 Q t-blocks.
// Row sums of E = exp(score/8)*mask accumulated in registers; written to
// g_part slots 0 (warps wn=0) and 1 (wn=1).
// smem: [0,16K) Khi | [16K,32K) Klo | [32K,48K) Qhi | [48K,64K) Qlo
//       | [64K,+512) fmask
// ---------------------------------------------------------------------------
#define ROWS_DSMEM (65536 + 512)

__global__ __launch_bounds__(256) void rows_kernel(const int* __restrict__ mask)
{
    extern __shared__ char sm[];
    const uint32_t sb = s2u(sm);
    float* fmask = (float*)(sm + 65536);

    const int bh = blockIdx.y;
    const int s0 = blockIdx.x * 128;
    const int b = bh / H_NUM;
    const int tid = threadIdx.x;
    const int w = tid >> 5, lane = tid & 31;
    const int wm = w & 3, wn = w >> 2;
    const int q8 = lane >> 3, r8 = lane & 7;
    const int g4 = lane >> 2, l4 = lane & 3;

    // stage K tiles (planes 0,1) once
#pragma unroll
    for (int u = 0; u < 8; u++) {
        const int id = tid + u * 256;
        const int T = id >> 10;
        const int r = (id >> 3) & 127;
        const int c = id & 7;
        const __nv_bfloat16* src = g_cvt + (size_t)T * PLANE_ELEMS
            + ((size_t)bh * S_DIM + s0 + r) * D_DIM + c * 8;
        CP16(sb + T * 16384 + swz128(r * 128 + c * 16), src);
    }
    CP_COMMIT();

    float acc[2][2] = {{0.f, 0.f}, {0.f, 0.f}};   // [m][rowpair]

    for (int tb = 0; tb < 8; tb++) {
        // stage Q tiles for this t-block (planes 2,3) + fmask
#pragma unroll
        for (int u = 0; u < 8; u++) {
            const int id = tid + u * 256;
            const int T = id >> 10;
            const int r = (id >> 3) & 127;
            const int c = id & 7;
            const __nv_bfloat16* src = g_cvt + (size_t)(2 + T) * PLANE_ELEMS
                + ((size_t)bh * S_DIM + tb * 128 + r) * D_DIM + c * 8;
            CP16(sb + 32768 + T * 16384 + swz128(r * 128 + c * 16), src);
        }
        CP_COMMIT();
        if (tid < 128) fmask[tid] = mask[b * S_DIM + tb * 128 + tid] ? 1.0f : 0.0f;
        asm volatile("cp.async.wait_group 0;");
        __syncthreads();

        float c[2][8][4];
#pragma unroll
        for (int m = 0; m < 2; m++)
#pragma unroll
            for (int n = 0; n < 8; n++)
#pragma unroll
                for (int i = 0; i < 4; i++) c[m][n][i] = 0.f;

#pragma unroll
        for (int ks = 0; ks < 4; ks++) {
            uint32_t ah[2][4], al[2][4], bh2[8][2], bl2[8][2];
#pragma unroll
            for (int m = 0; m < 2; m++) {
                const int rowA = wm * 32 + m * 16 + ((q8 & 1) << 3) + r8;
                const uint32_t off = swz128(rowA * 128 + (2 * ks + (q8 >> 1)) * 16);
                ldsm4(ah[m], sb + off);
                ldsm4(al[m], sb + 16384 + off);
            }
#pragma unroll
            for (int np = 0; np < 4; np++) {
                const int rowB = wn * 64 + np * 16 + ((q8 >> 1) << 3) + r8;
                const uint32_t off = swz128(rowB * 128 + (2 * ks + (q8 & 1)) * 16);
                uint32_t tmp[4];
                ldsm4(tmp, sb + 32768 + off);
                bh2[np * 2][0] = tmp[0]; bh2[np * 2][1] = tmp[1];
                bh2[np * 2 + 1][0] = tmp[2]; bh2[np * 2 + 1][1] = tmp[3];
                ldsm4(tmp, sb + 49152 + off);
                bl2[np * 2][0] = tmp[0]; bl2[np * 2][1] = tmp[1];
                bl2[np * 2 + 1][0] = tmp[2]; bl2[np * 2 + 1][1] = tmp[3];
            }
#pragma unroll
            for (int m = 0; m < 2; m++)
#pragma unroll
                for (int n = 0; n < 8; n++) {
                    mma16816(c[m][n], ah[m], bh2[n]);
                    mma16816(c[m][n], ah[m], bl2[n]);
                    mma16816(c[m][n], al[m], bh2[n]);
                }
        }

        // epilogue: exp*mask -> accumulate row sums
#pragma unroll
        for (int m = 0; m < 2; m++)
#pragma unroll
            for (int n = 0; n < 8; n++) {
                const int cn = wn * 64 + n * 8 + l4 * 2;
                const float f0 = fmask[cn], f1 = fmask[cn + 1];
                acc[m][0] += __expf(c[m][n][0] * 0.125f) * f0
                           + __expf(c[m][n][1] * 0.125f) * f1;
                acc[m][1] += __expf(c[m][n][2] * 0.125f) * f0
                           + __expf(c[m][n][3] * 0.125f) * f1;
            }
        __syncthreads();   // done reading Q tiles + fmask
    }

    // reduce over l4 lanes (same row), write slot wn
#pragma unroll
    for (int m = 0; m < 2; m++)
#pragma unroll
        for (int p = 0; p < 2; p++) {
            float v = acc[m][p];
            v += __shfl_xor_sync(0xffffffffu, v, 1);
            v += __shfl_xor_sync(0xffffffffu, v, 2);
            acc[m][p] = v;
        }
    if (l4 == 0) {
        float* pp = &g_part[((wn * NBH + bh) << 10) + s0];
        pp[wm * 32 + g4]      = acc[0][0];
        pp[wm * 32 + g4 + 8]  = acc[0][1];
        pp[wm * 32 + g4 + 16] = acc[1][0];
        pp[wm * 32 + g4 + 24] = acc[1][1];
    }
}

// ---------------------------------------------------------------------------
// vsplit_kernel: inv = 1/(slot0+slot1); writes inv*V bf16 hi/lo planes + g_inv.
// ---------------------------------------------------------------------------
__global__ __launch_bounds__(256) void vsplit_kernel(const float* __restrict__ V)
{
    __shared__ float inv[256];
    const int bh = blockIdx.y;
    const int q = blockIdx.x;
    const int tid = threadIdx.x;
    {
        const float sum = g_part[((0 * NBH + bh) << 10) + q * 256 + tid]
                        + g_part[((1 * NBH + bh) << 10) + q * 256 + tid];
        const float iv = 1.0f / sum;
        inv[tid] = iv;
        g_inv[bh * S_DIM + q * 256 + tid] = iv;
    }
    __syncthreads();

    const float* Vb = V + (size_t)bh * D_DIM * S_DIM + q * 256;
    __nv_bfloat16* Hh = g_Vh + (size_t)bh * D_DIM * S_DIM + q * 256;
    __nv_bfloat16* Hl = g_Vl + (size_t)bh * D_DIM * S_DIM + q * 256;

#pragma unroll
    for (int u = 0; u < 16; u++) {
        const int f = tid + u * 256;
        const int dr = f >> 6;
        const int c4 = (f & 63) * 4;
        float4 v = *(const float4*)&Vb[(size_t)dr * S_DIM + c4];
        const float4 iv = *(const float4*)&inv[c4];
        v.x *= iv.x; v.y *= iv.y; v.z *= iv.z; v.w *= iv.w;
        const uint32_t h01 = cvt2(v.x, v.y);
        const uint32_t h23 = cvt2(v.z, v.w);
        const float hx = __uint_as_float(h01 << 16);
        const float hy = __uint_as_float(h01 & 0xFFFF0000u);
        const float hz = __uint_as_float(h23 << 16);
        const float hw = __uint_as_float(h23 & 0xFFFF0000u);
        const uint32_t l01 = cvt2(v.x - hx, v.y - hy);
        const uint32_t l23 = cvt2(v.z - hz, v.w - hw);
        *(uint2*)&Hh[(size_t)dr * S_DIM + c4] = make_uint2(h01, h23);
        *(uint2*)&Hl[(size_t)dr * S_DIM + c4] = make_uint2(l01, l23);
    }
}

// ---------------------------------------------------------------------------
// pv2_kernel: per (t-tile 128, bh). Q tiles staged once. Per 32-s chunk:
//  phase1: QK MMA recompute -> exp*mask -> bf16 hi/lo E in smem
//  phase2: PV MMA (3-pass) + attn writeback (hi+lo)*inv
// K/V chunks double-buffered via cp.async.
// smem: 0 Qhi 16K | 16K Qlo | 32K Khi[2][4K] | 40K Klo[2][4K]
//       | 48K+1K=49152 Vh[2][5120] | 59392 Vl[2][5120]
//       | 69632 Ehi[32][272] 8704 | 78336 Elo 8704 | 87040 inv 4096
//       | 91136 fmask 512   total 91648. Cs[128][66] f32 aliases base.
// ---------------------------------------------------------------------------
#define PV2_DSMEM 91648

__global__ __launch_bounds__(256, 2) void pv2_kernel(
    const int* __restrict__ mask, float* __restrict__ attn, float* __restrict__ ctx)
{
    extern __shared__ char sm[];
    const uint32_t sb = s2u(sm);
    const uint32_t uKh = sb + 32768, uKl = sb + 40960;
    const uint32_t uVh = sb + 49152, uVl = sb + 59392;
    const uint32_t uEh = sb + 69632, uEl = sb + 78336;
    float* invs  = (float*)(sm + 87040);
    float* fmask = (float*)(sm + 91136);
    float* Cs = (float*)sm;

    const int bh = blockIdx.y;
    const int t0 = blockIdx.x * 128;
    const int b = bh / H_NUM;
    const int h = bh - b * H_NUM;
    const __nv_bfloat16* Khg = g_cvt + (size_t)bh * S_DIM * D_DIM;                    // plane 0
    const __nv_bfloat16* Klg = g_cvt + PLANE_ELEMS + (size_t)bh * S_DIM * D_DIM;      // plane 1
    const __nv_bfloat16* Vhg = g_Vh + (size_t)bh * D_DIM * S_DIM;
    const __nv_bfloat16* Vlg = g_Vl + (size_t)bh * D_DIM * S_DIM;
    float* Ab = attn + (size_t)bh * S_DIM * S_DIM;

    const int tid = threadIdx.x;
    const int w = tid >> 5, lane = tid & 31;
    const int wm = w & 3, wn = w >> 2;
    const int q8 = lane >> 3, r8 = lane & 7;
    const int g4 = lane >> 2, l4 = lane & 3;
    const int cs = tid >> 3, cq = tid & 7;      // attn writeback map
    const int kr = tid >> 3, kc = tid & 7;      // K chunk cp map
    const int vrow = tid >> 2, vc = tid & 3;    // V chunk cp map

    // stage Q tiles (planes 2,3) once
#pragma unroll
    for (int u = 0; u < 8; u++) {
        const int id = tid + u * 256;
        const int T = id >> 10;
        const int r = (id >> 3) & 127;
        const int c = id & 7;
        const __nv_bfloat16* src = g_cvt + (size_t)(2 + T) * PLANE_ELEMS
            + ((size_t)bh * S_DIM + t0 + r) * D_DIM + c * 8;
        CP16(sb + T * 16384 + swz128(r * 128 + c * 16), src);
    }
    CP_COMMIT();   // G_Q

#define CPKV(ci, buf)                                                          \
    {                                                                          \
        CP16(uKh + (buf) * 4096 + swz128(kr * 128 + kc * 16),                  \
             Khg + (size_t)((ci) * 32 + kr) * D_DIM + kc * 8);                 \
        CP16(uKl + (buf) * 4096 + swz128(kr * 128 + kc * 16),                  \
             Klg + (size_t)((ci) * 32 + kr) * D_DIM + kc * 8);                 \
        CP16(uVh + (buf) * 5120 + vrow * 80 + vc * 16,                         \
             Vhg + (size_t)vrow * S_DIM + (ci) * 32 + vc * 8);                 \
        CP16(uVl + (buf) * 5120 + vrow * 80 + vc * 16,                         \
             Vlg + (size_t)vrow * S_DIM + (ci) * 32 + vc * 8);                 \
        CP_COMMIT();                                                           \
    }

    CPKV(0, 0);   // G_0
    CPKV(1, 1);   // G_1

    // inv + fmask
#pragma unroll
    for (int j = 0; j < 4; j++)
        invs[tid + j * 256] = g_inv[bh * S_DIM + tid + j * 256];
    if (tid < 128) fmask[tid] = mask[b * S_DIM + t0 + tid] ? 1.0f : 0.0f;

    asm volatile("cp.async.wait_group %0;" :: "n"(1));   // G_Q, G_0 done
    __syncthreads();

    float c[8][4];
#pragma unroll
    for (int n = 0; n < 8; n++)
#pragma unroll
        for (int i = 0; i < 4; i++) c[n][i] = 0.f;

    for (int ci = 0; ci < 32; ci++) {
        const int cur = ci & 1;

        // ---- phase 1: QK recompute for chunk ci -> E hi/lo smem ----
        {
            float c2[2][2][4];
#pragma unroll
            for (int m = 0; m < 2; m++)
#pragma unroll
                for (int n = 0; n < 2; n++)
#pragma unroll
                    for (int i = 0; i < 4; i++) c2[m][n][i] = 0.f;

#pragma unroll
            for (int ks = 0; ks < 4; ks++) {
                uint32_t ah[2][4], al[2][4], bqh[2][2], bql[2][2];
#pragma unroll
                for (int m = 0; m < 2; m++) {
                    const int rowA = m * 16 + ((q8 & 1) << 3) + r8;
                    const uint32_t off = swz128(rowA * 128 + (2 * ks + (q8 >> 1)) * 16)
                                       + cur * 4096;
                    ldsm4(ah[m], uKh + off);
                    ldsm4(al[m], uKl + off);
                }
                {
                    const int rowB = w * 16 + ((q8 >> 1) << 3) + r8;
                    const uint32_t off = swz128(rowB * 128 + (2 * ks + (q8 & 1)) * 16);
                    uint32_t tmp[4];
                    ldsm4(tmp, sb + off);              // Qhi
                    bqh[0][0] = tmp[0]; bqh[0][1] = tmp[1];
                    bqh[1][0] = tmp[2]; bqh[1][1] = tmp[3];
                    ldsm4(tmp, sb + 16384 + off);      // Qlo
                    bql[0][0] = tmp[0]; bql[0][1] = tmp[1];
                    bql[1][0] = tmp[2]; bql[1][1] = tmp[3];
                }
#pragma unroll
                for (int m = 0; m < 2; m++)
#pragma unroll
                    for (int n = 0; n < 2; n++) {
                        mma16816(c2[m][n], ah[m], bqh[n]);
                        mma16816(c2[m][n], ah[m], bql[n]);
                        mma16816(c2[m][n], al[m], bqh[n]);
                    }
            }
            // exp*mask -> split -> STS E (conflict-free: bank = g4*4+l4 pattern)
#pragma unroll
            for (int m = 0; m < 2; m++)
#pragma unroll
                for (int n = 0; n < 2; n++) {
                    const int rm = m * 16 + g4;
                    const int cn = w * 16 + n * 8 + l4 * 2;
                    const float f0 = fmask[cn], f1 = fmask[cn + 1];
                    const float e0 = __expf(c2[m][n][0] * 0.125f) * f0;
                    const float e1 = __expf(c2[m][n][1] * 0.125f) * f1;
                    const float e2 = __expf(c2[m][n][2] * 0.125f) * f0;
                    const float e3 = __expf(c2[m][n][3] * 0.125f) * f1;
                    const uint32_t h01 = cvt2(e0, e1);
                    const uint32_t h23 = cvt2(e2, e3);
                    const uint32_t l01 = cvt2(e0 - __uint_as_float(h01 << 16),
                                              e1 - __uint_as_float(h01 & 0xFFFF0000u));
                    const uint32_t l23 = cvt2(e2 - __uint_as_float(h23 << 16),
                                              e3 - __uint_as_float(h23 & 0xFFFF0000u));
                    *(uint32_t*)(sm + 69632 + rm * 272 + cn * 2) = h01;
                    *(uint32_t*)(sm + 78336 + rm * 272 + cn * 2) = l01;
                    *(uint32_t*)(sm + 69632 + (rm + 8) * 272 + cn * 2) = h23;
                    *(uint32_t*)(sm + 78336 + (rm + 8) * 272 + cn * 2) = l23;
                }
        }
        __syncthreads();   // E ready

        // ---- phase 2: PV MMA (validated fragment code) ----
#pragma unroll
        for (int ks = 0; ks < 2; ks++) {
            uint32_t ah[4], al[4];
            const uint32_t aoff =
                (uint32_t)(wm * 16 + ((q8 & 1) << 3) + r8) * 80 + ks * 32 + (q8 >> 1) * 16
                + cur * 5120;
            ldsm4(ah, uVh + aoff);
            ldsm4(al, uVl + aoff);
            uint32_t bhf[8][2], blf[8][2];
#pragma unroll
            for (int tp = 0; tp < 4; tp++) {
                const uint32_t boff =
                    (uint32_t)(ks * 16 + ((q8 & 1) << 3) + r8) * 272
                    + (wn * 64 + tp * 16) * 2 + (q8 >> 1) * 16;
                uint32_t tmp[4];
                ldsm4t(tmp, uEh + boff);
                bhf[tp * 2][0] = tmp[0]; bhf[tp * 2][1] = tmp[1];
                bhf[tp * 2 + 1][0] = tmp[2]; bhf[tp * 2 + 1][1] = tmp[3];
                ldsm4t(tmp, uEl + boff);
                blf[tp * 2][0] = tmp[0]; blf[tp * 2][1] = tmp[1];
                blf[tp * 2 + 1][0] = tmp[2]; blf[tp * 2 + 1][1] = tmp[3];
            }
#pragma unroll
            for (int n = 0; n < 8; n++) {
                mma16816(c[n], ah, bhf[n]);
                mma16816(c[n], ah, blf[n]);
                mma16816(c[n], al, bhf[n]);
            }
        }

        // ---- attn writeback: (hi+lo)*inv ----
        {
            const float iv = invs[ci * 32 + cs];
            const uint32_t sb2 = cs * 272 + cq * 32;
            const uint4 H0 = *(const uint4*)(sm + 69632 + sb2);
            const uint4 H1 = *(const uint4*)(sm + 69632 + sb2 + 16);
            const uint4 L0 = *(const uint4*)(sm + 78336 + sb2);
            const uint4 L1 = *(const uint4*)(sm + 78336 + sb2 + 16);
            const uint32_t hs[8] = {H0.x, H0.y, H0.z, H0.w, H1.x, H1.y, H1.z, H1.w};
            const uint32_t ls[8] = {L0.x, L0.y, L0.z, L0.w, L1.x, L1.y, L1.z, L1.w};
            float* op = &Ab[(size_t)(ci * 32 + cs) * S_DIM + t0 + cq * 16];
#pragma unroll
            for (int i = 0; i < 4; i++) {
                float4 a4;
                a4.x = (__uint_as_float(hs[2 * i] << 16)
                        + __uint_as_float(ls[2 * i] << 16)) * iv;
                a4.y = (__uint_as_float(hs[2 * i] & 0xFFFF0000u)
                        + __uint_as_float(ls[2 * i] & 0xFFFF0000u)) * iv;
                a4.z = (__uint_as_float(hs[2 * i + 1] << 16)
                        + __uint_as_float(ls[2 * i + 1] << 16)) * iv;
                a4.w = (__uint_as_float(hs[2 * i + 1] & 0xFFFF0000u)
                        + __uint_as_float(ls[2 * i + 1] & 0xFFFF0000u)) * iv;
                *(float4*)(op + i * 4) = a4;
            }
        }
        if (ci == 31) break;

        __syncthreads();   // all reads of K/V[cur] + E done
        if (ci + 2 < 32) {
            CPKV(ci + 2, cur);
            asm volatile("cp.async.wait_group %0;" :: "n"(1));
        } else {
            asm volatile("cp.async.wait_group %0;" :: "n"(0));
        }
        __syncthreads();   // K/V[nxt] visible
    }

    // ---- ctx epilogue ----
    __syncthreads();
#pragma unroll
    for (int n = 0; n < 8; n++) {
        const int tb = wn * 64 + n * 8 + l4 * 2;
        const int d0 = wm * 16 + g4;
        Cs[tb * 66 + d0]           = c[n][0];
        Cs[(tb + 1) * 66 + d0]     = c[n][1];
        Cs[tb * 66 + d0 + 8]       = c[n][2];
        Cs[(tb + 1) * 66 + d0 + 8] = c[n][3];
    }
    __syncthreads();
#pragma unroll
    for (int rr = 0; rr < 16; rr++) {
        const int t = w * 16 + rr;
        const float2 v = *(const float2*)&Cs[t * 66 + lane * 2];
        *(float2*)&ctx[((size_t)b * S_DIM + t0 + t) * (H_NUM * D_DIM)
                       + h * D_DIM + lane * 2] = v;
    }
}

// ---------------------------------------------------------------------------
extern "C" void kernel_launch(void* const* d_in, const int* in_sizes, int n_in,
                              void* d_out, int out_size)
{
    (void)in_sizes; (void)n_in; (void)out_size;
    const float* Q = (const float*)d_in[0];
    const float* K = (const float*)d_in[1];
    const float* V = (const float*)d_in[2];
    const int* mask = (const int*)d_in[3];

    float* ctx  = (float*)d_out;                 // (B, S, H*D)
    float* attn = ctx + CTX_ELEMS;               // (B, H, S, S)

    static int attr_set = 0;
    if (!attr_set) {
        cudaFuncSetAttribute(rows_kernel, cudaFuncAttributeMaxDynamicSharedMemorySize,
                             ROWS_DSMEM);
        cudaFuncSetAttribute(pv2_kernel, cudaFuncAttributeMaxDynamicSharedMemorySize,
                             PV2_DSMEM);
        attr_set = 1;
    }

    convert_kernel<<<dim3(16, NBH, 2), 256>>>(K, Q);
    rows_kernel<<<dim3(8, NBH), 256, ROWS_DSMEM>>>(mask);
    vsplit_kernel<<<dim3(4, NBH), 256>>>(V);
    pv2_kernel<<<dim3(8, NBH), 256, PV2_DSMEM>>>(mask, attn, ctx);
}

// round 14
// speedup vs baseline: 2.1691x; 1.0078x over previous
#include <cuda_runtime.h>
#include <cuda_bf16.h>
#include <cstdint>

// Shapes (fixed): B=8, H=12, D=64, S=1024
// scores[b,h,s,t] = (1/8) * sum_d K[b,h,d,s] * Q[b,h,d,t]
// mask over t (per b), softmax over t, context[b,h,d,t] = sum_s V[b,h,d,s]*attn[b,h,s,t]
// out = concat( context as (B,S,H*D), attn as (B,H,S,S) )
//
// convert_kernel : K,Q fp32 [bh][d][s] -> bf16 hi/lo planes [bh][s][d].
// rows_kernel    : per (s-tile, bh): QK MMA over all t, exp*mask, row sums.
// vsplit_kernel  : inv = 1/rowsum; writes inv*V bf16 hi/lo planes + g_inv.
// pv3_kernel     : software-pipelined: phase1 computes E(ci+1) (QK MMA + exp
//                  -> bf16 hi/lo smem, double-buffered) WHILE phase2 runs
//                  PV MMA on E(ci); attn written from E smem.

#define D_DIM 64
#define S_DIM 1024
#define H_NUM 12
#define B_NUM 8
#define NBH   (B_NUM * H_NUM)
#define CTX_ELEMS ((size_t)B_NUM * S_DIM * H_NUM * D_DIM)   // 6291456
#define PLANE_ELEMS (NBH * S_DIM * D_DIM)                    // 6291456

__device__ __forceinline__ unsigned s2u(const void* p) {
    return (unsigned)__cvta_generic_to_shared(p);
}
__device__ __forceinline__ uint32_t swz128(uint32_t off) {
    return off ^ ((off >> 3) & 0x70);
}
__device__ __forceinline__ void ldsm4(uint32_t* r, uint32_t addr) {
    asm volatile("ldmatrix.sync.aligned.m8n8.x4.shared.b16 {%0,%1,%2,%3}, [%4];"
                 : "=r"(r[0]), "=r"(r[1]), "=r"(r[2]), "=r"(r[3]) : "r"(addr));
}
__device__ __forceinline__ void ldsm4t(uint32_t* r, uint32_t addr) {
    asm volatile("ldmatrix.sync.aligned.m8n8.x4.trans.shared.b16 {%0,%1,%2,%3}, [%4];"
                 : "=r"(r[0]), "=r"(r[1]), "=r"(r[2]), "=r"(r[3]) : "r"(addr));
}
__device__ __forceinline__ void mma16816(float* c, const uint32_t* a, const uint32_t* b) {
    asm volatile(
        "mma.sync.aligned.m16n8k16.row.col.f32.bf16.bf16.f32 "
        "{%0,%1,%2,%3}, {%4,%5,%6,%7}, {%8,%9}, {%0,%1,%2,%3};"
        : "+f"(c[0]), "+f"(c[1]), "+f"(c[2]), "+f"(c[3])
        : "r"(a[0]), "r"(a[1]), "r"(a[2]), "r"(a[3]), "r"(b[0]), "r"(b[1]));
}
__device__ __forceinline__ uint32_t cvt2(float lo, float hi) {
    uint32_t r;
    asm("cvt.rn.bf16x2.f32 %0, %1, %2;" : "=r"(r) : "f"(hi), "f"(lo));
    return r;
}
#define CP16(dst_u, src_p) \
    asm volatile("cp.async.cg.shared.global [%0], [%1], 16;" :: "r"(dst_u), "l"(src_p))
#define CP_COMMIT() asm volatile("cp.async.commit_group;")

// ---------------- global scratch ----------------
__device__ __nv_bfloat16 g_cvt[4 * PLANE_ELEMS];     // 0=Khi 1=Klo 2=Qhi 3=Qlo [bh][s][d]
__device__ float g_part[8 * NBH * S_DIM];            // [slot(2)][bh][s]
__device__ __nv_bfloat16 g_Vh[PLANE_ELEMS];          // inv*V hi [bh][d][s]
__device__ __nv_bfloat16 g_Vl[PLANE_ELEMS];
__device__ float g_inv[NBH * S_DIM];

// ---------------------------------------------------------------------------
// convert_kernel (unchanged)
// ---------------------------------------------------------------------------
__global__ __launch_bounds__(256) void convert_kernel(
    const float* __restrict__ K, const float* __restrict__ Q)
{
    const int z = blockIdx.z;
    const int bh = blockIdx.y;
    const int s0 = blockIdx.x * 64;
    const float* X = z ? Q : K;
    __nv_bfloat16* hiP = g_cvt + (size_t)(z * 2) * PLANE_ELEMS;
    __nv_bfloat16* loP = g_cvt + (size_t)(z * 2 + 1) * PLANE_ELEMS;

    __shared__ float t[64][68];
    const int tid = threadIdx.x;

#pragma unroll
    for (int j = 0; j < 4; j++) {
        const int d = (tid >> 4) + j * 16;
        const int s = (tid & 15) * 4;
        const float4 v = *(const float4*)&X[(((size_t)bh * 64 + d) << 10) + s0 + s];
        t[d][s + 0] = v.x; t[d][s + 1] = v.y; t[d][s + 2] = v.z; t[d][s + 3] = v.w;
    }
    __syncthreads();

    const int sl = tid >> 2;
    const int dq = (tid & 3) * 16;
    __align__(16) __nv_bfloat16 hb[16], lb[16];
#pragma unroll
    for (int q = 0; q < 16; q++) {
        const float x = t[dq + q][sl];
        const __nv_bfloat16 h = __float2bfloat16_rn(x);
        hb[q] = h;
        lb[q] = __float2bfloat16_rn(x - __bfloat162float(h));
    }
    const size_t o = ((size_t)bh * S_DIM + s0 + sl) * D_DIM + dq;
    *(uint4*)&hiP[o]     = *(const uint4*)&hb[0];
    *(uint4*)&hiP[o + 8] = *(const uint4*)&hb[8];
    *(uint4*)&loP[o]     = *(const uint4*)&lb[0];
    *(uint4*)&loP[o + 8] = *(const uint4*)&lb[8];
}

// ---------------------------------------------------------------------------
// rows_kernel (unchanged R13)
// ---------------------------------------------------------------------------
#define ROWS_DSMEM (65536 + 512)

__global__ __launch_bounds__(256) void rows_kernel(const int* __restrict__ mask)
{
    extern __shared__ char sm[];
    const uint32_t sb = s2u(sm);
    float* fmask = (float*)(sm + 65536);

    const int bh = blockIdx.y;
    const int s0 = blockIdx.x * 128;
    const int b = bh / H_NUM;
    const int tid = threadIdx.x;
    const int w = tid >> 5, lane = tid & 31;
    const int wm = w & 3, wn = w >> 2;
    const int q8 = lane >> 3, r8 = lane & 7;
    const int g4 = lane >> 2, l4 = lane & 3;

#pragma unroll
    for (int u = 0; u < 8; u++) {
        const int id = tid + u * 256;
        const int T = id >> 10;
        const int r = (id >> 3) & 127;
        const int c = id & 7;
        const __nv_bfloat16* src = g_cvt + (size_t)T * PLANE_ELEMS
            + ((size_t)bh * S_DIM + s0 + r) * D_DIM + c * 8;
        CP16(sb + T * 16384 + swz128(r * 128 + c * 16), src);
    }
    CP_COMMIT();

    float acc[2][2] = {{0.f, 0.f}, {0.f, 0.f}};

    for (int tb = 0; tb < 8; tb++) {
#pragma unroll
        for (int u = 0; u < 8; u++) {
            const int id = tid + u * 256;
            const int T = id >> 10;
            const int r = (id >> 3) & 127;
            const int c = id & 7;
            const __nv_bfloat16* src = g_cvt + (size_t)(2 + T) * PLANE_ELEMS
                + ((size_t)bh * S_DIM + tb * 128 + r) * D_DIM + c * 8;
            CP16(sb + 32768 + T * 16384 + swz128(r * 128 + c * 16), src);
        }
        CP_COMMIT();
        if (tid < 128) fmask[tid] = mask[b * S_DIM + tb * 128 + tid] ? 1.0f : 0.0f;
        asm volatile("cp.async.wait_group 0;");
        __syncthreads();

        float c[2][8][4];
#pragma unroll
        for (int m = 0; m < 2; m++)
#pragma unroll
            for (int n = 0; n < 8; n++)
#pragma unroll
                for (int i = 0; i < 4; i++) c[m][n][i] = 0.f;

#pragma unroll
        for (int ks = 0; ks < 4; ks++) {
            uint32_t ah[2][4], al[2][4], bh2[8][2], bl2[8][2];
#pragma unroll
            for (int m = 0; m < 2; m++) {
                const int rowA = wm * 32 + m * 16 + ((q8 & 1) << 3) + r8;
                const uint32_t off = swz128(rowA * 128 + (2 * ks + (q8 >> 1)) * 16);
                ldsm4(ah[m], sb + off);
                ldsm4(al[m], sb + 16384 + off);
            }
#pragma unroll
            for (int np = 0; np < 4; np++) {
                const int rowB = wn * 64 + np * 16 + ((q8 >> 1) << 3) + r8;
                const uint32_t off = swz128(rowB * 128 + (2 * ks + (q8 & 1)) * 16);
                uint32_t tmp[4];
                ldsm4(tmp, sb + 32768 + off);
                bh2[np * 2][0] = tmp[0]; bh2[np * 2][1] = tmp[1];
                bh2[np * 2 + 1][0] = tmp[2]; bh2[np * 2 + 1][1] = tmp[3];
                ldsm4(tmp, sb + 49152 + off);
                bl2[np * 2][0] = tmp[0]; bl2[np * 2][1] = tmp[1];
                bl2[np * 2 + 1][0] = tmp[2]; bl2[np * 2 + 1][1] = tmp[3];
            }
#pragma unroll
            for (int m = 0; m < 2; m++)
#pragma unroll
                for (int n = 0; n < 8; n++) {
                    mma16816(c[m][n], ah[m], bh2[n]);
                    mma16816(c[m][n], ah[m], bl2[n]);
                    mma16816(c[m][n], al[m], bh2[n]);
                }
        }

#pragma unroll
        for (int m = 0; m < 2; m++)
#pragma unroll
            for (int n = 0; n < 8; n++) {
                const int cn = wn * 64 + n * 8 + l4 * 2;
                const float f0 = fmask[cn], f1 = fmask[cn + 1];
                acc[m][0] += __expf(c[m][n][0] * 0.125f) * f0
                           + __expf(c[m][n][1] * 0.125f) * f1;
                acc[m][1] += __expf(c[m][n][2] * 0.125f) * f0
                           + __expf(c[m][n][3] * 0.125f) * f1;
            }
        __syncthreads();
    }

#pragma unroll
    for (int m = 0; m < 2; m++)
#pragma unroll
        for (int p = 0; p < 2; p++) {
            float v = acc[m][p];
            v += __shfl_xor_sync(0xffffffffu, v, 1);
            v += __shfl_xor_sync(0xffffffffu, v, 2);
            acc[m][p] = v;
        }
    if (l4 == 0) {
        float* pp = &g_part[((wn * NBH + bh) << 10) + s0];
        pp[wm * 32 + g4]      = acc[0][0];
        pp[wm * 32 + g4 + 8]  = acc[0][1];
        pp[wm * 32 + g4 + 16] = acc[1][0];
        pp[wm * 32 + g4 + 24] = acc[1][1];
    }
}

// ---------------------------------------------------------------------------
// vsplit_kernel (unchanged R13)
// ---------------------------------------------------------------------------
__global__ __launch_bounds__(256) void vsplit_kernel(const float* __restrict__ V)
{
    __shared__ float inv[256];
    const int bh = blockIdx.y;
    const int q = blockIdx.x;
    const int tid = threadIdx.x;
    {
        const float sum = g_part[((0 * NBH + bh) << 10) + q * 256 + tid]
                        + g_part[((1 * NBH + bh) << 10) + q * 256 + tid];
        const float iv = 1.0f / sum;
        inv[tid] = iv;
        g_inv[bh * S_DIM + q * 256 + tid] = iv;
    }
    __syncthreads();

    const float* Vb = V + (size_t)bh * D_DIM * S_DIM + q * 256;
    __nv_bfloat16* Hh = g_Vh + (size_t)bh * D_DIM * S_DIM + q * 256;
    __nv_bfloat16* Hl = g_Vl + (size_t)bh * D_DIM * S_DIM + q * 256;

#pragma unroll
    for (int u = 0; u < 16; u++) {
        const int f = tid + u * 256;
        const int dr = f >> 6;
        const int c4 = (f & 63) * 4;
        float4 v = *(const float4*)&Vb[(size_t)dr * S_DIM + c4];
        const float4 iv = *(const float4*)&inv[c4];
        v.x *= iv.x; v.y *= iv.y; v.z *= iv.z; v.w *= iv.w;
        const uint32_t h01 = cvt2(v.x, v.y);
        const uint32_t h23 = cvt2(v.z, v.w);
        const float hx = __uint_as_float(h01 << 16);
        const float hy = __uint_as_float(h01 & 0xFFFF0000u);
        const float hz = __uint_as_float(h23 << 16);
        const float hw = __uint_as_float(h23 & 0xFFFF0000u);
        const uint32_t l01 = cvt2(v.x - hx, v.y - hy);
        const uint32_t l23 = cvt2(v.z - hz, v.w - hw);
        *(uint2*)&Hh[(size_t)dr * S_DIM + c4] = make_uint2(h01, h23);
        *(uint2*)&Hl[(size_t)dr * S_DIM + c4] = make_uint2(l01, l23);
    }
}

// ---------------------------------------------------------------------------
// pv3_kernel: software-pipelined pv2. Per iter ci:
//   a) issue cp K(ci+2) -> Kbuf[cur]   (K[cur] dead: phase1 reads K[nxt])
//   b) phase1: E(ci+1) = QK(ci+1) via K[nxt] -> Ebuf[nxt]    (look-ahead)
//   c) phase2: PV(ci) via Ebuf[cur], V[cur]; attn writeback from Ebuf[cur]
//   d) sync; e) issue cp V(ci+2) -> Vbuf[cur]; wait_group(1); f) sync
// smem: 0 Qhi 16K | 16K Qlo | 32768 Kh[2][4096] | 40960 Kl[2][4096]
//       | 49152 Vh[2][5120] | 59392 Vl[2][5120]
//       | 69632 Eh[2][8704] | 87040 El[2][8704] | 104448 invs 4096
// total 108544. Cs[128][66] f32 aliases base. fmask lives in 4 registers.
// ---------------------------------------------------------------------------
#define PV3_DSMEM 108544

__global__ __launch_bounds__(256, 2) void pv3_kernel(
    const int* __restrict__ mask, float* __restrict__ attn, float* __restrict__ ctx)
{
    extern __shared__ char sm[];
    const uint32_t sb = s2u(sm);
    const uint32_t uKh = sb + 32768, uKl = sb + 40960;
    const uint32_t uVh = sb + 49152, uVl = sb + 59392;
    float* invs = (float*)(sm + 104448);
    float* Cs = (float*)sm;

    const int bh = blockIdx.y;
    const int t0 = blockIdx.x * 128;
    const int b = bh / H_NUM;
    const int h = bh - b * H_NUM;
    const __nv_bfloat16* Khg = g_cvt + (size_t)bh * S_DIM * D_DIM;
    const __nv_bfloat16* Klg = g_cvt + PLANE_ELEMS + (size_t)bh * S_DIM * D_DIM;
    const __nv_bfloat16* Vhg = g_Vh + (size_t)bh * D_DIM * S_DIM;
    const __nv_bfloat16* Vlg = g_Vl + (size_t)bh * D_DIM * S_DIM;
    float* Ab = attn + (size_t)bh * S_DIM * S_DIM;

    const int tid = threadIdx.x;
    const int w = tid >> 5, lane = tid & 31;
    const int wm = w & 3, wn = w >> 2;
    const int q8 = lane >> 3, r8 = lane & 7;
    const int g4 = lane >> 2, l4 = lane & 3;
    const int cs = tid >> 3, cq = tid & 7;
    const int kr = tid >> 3, kc = tid & 7;
    const int vrow = tid >> 2, vc = tid & 3;

    // per-thread epilogue mask (columns fixed for all chunks)
    float fmr[2][2];
#pragma unroll
    for (int n = 0; n < 2; n++) {
        const int cn = w * 16 + n * 8 + l4 * 2;
        fmr[n][0] = mask[b * S_DIM + t0 + cn] ? 1.0f : 0.0f;
        fmr[n][1] = mask[b * S_DIM + t0 + cn + 1] ? 1.0f : 0.0f;
    }

    // stage Q tiles once
#pragma unroll
    for (int u = 0; u < 8; u++) {
        const int id = tid + u * 256;
        const int T = id >> 10;
        const int r = (id >> 3) & 127;
        const int c = id & 7;
        const __nv_bfloat16* src = g_cvt + (size_t)(2 + T) * PLANE_ELEMS
            + ((size_t)bh * S_DIM + t0 + r) * D_DIM + c * 8;
        CP16(sb + T * 16384 + swz128(r * 128 + c * 16), src);
    }
    CP_COMMIT();

#define CPK(ci, buf)                                                           \
    {                                                                          \
        CP16(uKh + (buf) * 4096 + swz128(kr * 128 + kc * 16),                  \
             Khg + (size_t)((ci) * 32 + kr) * D_DIM + kc * 8);                 \
        CP16(uKl + (buf) * 4096 + swz128(kr * 128 + kc * 16),                  \
             Klg + (size_t)((ci) * 32 + kr) * D_DIM + kc * 8);                 \
        CP_COMMIT();                                                           \
    }
#define CPV(ci, buf)                                                           \
    {                                                                          \
        CP16(uVh + (buf) * 5120 + vrow * 80 + vc * 16,                         \
             Vhg + (size_t)vrow * S_DIM + (ci) * 32 + vc * 8);                 \
        CP16(uVl + (buf) * 5120 + vrow * 80 + vc * 16,                         \
             Vlg + (size_t)vrow * S_DIM + (ci) * 32 + vc * 8);                 \
        CP_COMMIT();                                                           \
    }

    CPK(0, 0); CPV(0, 0);
    CPK(1, 1); CPV(1, 1);

#pragma unroll
    for (int j = 0; j < 4; j++)
        invs[tid + j * 256] = g_inv[bh * S_DIM + tid + j * 256];

    asm volatile("cp.async.wait_group 0;");
    __syncthreads();

    // phase1 for chunk cc into E buffer eb using K buffer kb
#define PHASE1(cc, kb)                                                         \
    {                                                                          \
        float c2[2][2][4];                                                     \
        _Pragma("unroll")                                                      \
        for (int m = 0; m < 2; m++)                                            \
            _Pragma("unroll")                                                  \
            for (int n = 0; n < 2; n++)                                        \
                _Pragma("unroll")                                              \
                for (int i = 0; i < 4; i++) c2[m][n][i] = 0.f;                 \
        _Pragma("unroll")                                                      \
        for (int ks = 0; ks < 4; ks++) {                                       \
            uint32_t ah[2][4], al[2][4], bqh[2][2], bql[2][2];                 \
            _Pragma("unroll")                                                  \
            for (int m = 0; m < 2; m++) {                                      \
                const int rowA = m * 16 + ((q8 & 1) << 3) + r8;                \
                const uint32_t off = swz128(rowA * 128 + (2 * ks + (q8 >> 1)) * 16) \
                                   + (kb) * 4096;                              \
                ldsm4(ah[m], uKh + off);                                       \
                ldsm4(al[m], uKl + off);                                       \
            }                                                                  \
            {                                                                  \
                const int rowB = w * 16 + ((q8 >> 1) << 3) + r8;               \
                const uint32_t off = swz128(rowB * 128 + (2 * ks + (q8 & 1)) * 16); \
                uint32_t tmp[4];                                               \
                ldsm4(tmp, sb + off);                                          \
                bqh[0][0] = tmp[0]; bqh[0][1] = tmp[1];                        \
                bqh[1][0] = tmp[2]; bqh[1][1] = tmp[3];                        \
                ldsm4(tmp, sb + 16384 + off);                                  \
                bql[0][0] = tmp[0]; bql[0][1] = tmp[1];                        \
                bql[1][0] = tmp[2]; bql[1][1] = tmp[3];                        \
            }                                                                  \
            _Pragma("unroll")                                                  \
            for (int m = 0; m < 2; m++)                                        \
                _Pragma("unroll")                                              \
                for (int n = 0; n < 2; n++) {                                  \
                    mma16816(c2[m][n], ah[m], bqh[n]);                         \
                    mma16816(c2[m][n], ah[m], bql[n]);                         \
                    mma16816(c2[m][n], al[m], bqh[n]);                         \
                }                                                              \
        }                                                                      \
        const uint32_t ebo = 69632 + (size_t)0 + (eb) * 8704;                  \
        _Pragma("unroll")                                                      \
        for (int m = 0; m < 2; m++)                                            \
            _Pragma("unroll")                                                  \
            for (int n = 0; n < 2; n++) {                                      \
                const int rm = m * 16 + g4;                                    \
                const int cn = w * 16 + n * 8 + l4 * 2;                        \
                const float e0 = __expf(c2[m][n][0] * 0.125f) * fmr[n][0];     \
                const float e1 = __expf(c2[m][n][1] * 0.125f) * fmr[n][1];     \
                const float e2 = __expf(c2[m][n][2] * 0.125f) * fmr[n][0];     \
                const float e3 = __expf(c2[m][n][3] * 0.125f) * fmr[n][1];     \
                const uint32_t h01 = cvt2(e0, e1);                             \
                const uint32_t h23 = cvt2(e2, e3);                             \
                const uint32_t l01 = cvt2(e0 - __uint_as_float(h01 << 16),     \
                                          e1 - __uint_as_float(h01 & 0xFFFF0000u)); \
                const uint32_t l23 = cvt2(e2 - __uint_as_float(h23 << 16),     \
                                          e3 - __uint_as_float(h23 & 0xFFFF0000u)); \
                *(uint32_t*)(sm + ebo + rm * 272 + cn * 2) = h01;              \
                *(uint32_t*)(sm + ebo + 17408 + rm * 272 + cn * 2) = l01;      \
                *(uint32_t*)(sm + ebo + (rm + 8) * 272 + cn * 2) = h23;        \
                *(uint32_t*)(sm + ebo + 17408 + (rm + 8) * 272 + cn * 2) = l23; \
            }                                                                  \
    }

    // prologue: E(0) into buffer 0
    {
        const int eb = 0;
        PHASE1(0, 0);
    }
    __syncthreads();

    float c[8][4];
#pragma unroll
    for (int n = 0; n < 8; n++)
#pragma unroll
        for (int i = 0; i < 4; i++) c[n][i] = 0.f;

    for (int ci = 0; ci < 32; ci++) {
        const int cur = ci & 1, nxt = cur ^ 1;

        // a) prefetch K(ci+2) into K[cur] (dead this iteration)
        if (ci + 2 < 32) CPK(ci + 2, cur);

        // b) phase1: E(ci+1) look-ahead
        if (ci < 31) {
            const int eb = nxt;
            PHASE1(ci + 1, nxt);
        }

        // c) phase2: PV(ci) from E[cur], V[cur]
        const uint32_t uEhc = sb + 69632 + cur * 8704;
        const uint32_t uElc = uEhc + 17408;
#pragma unroll
        for (int ks = 0; ks < 2; ks++) {
            uint32_t ah[4], al[4];
            const uint32_t aoff =
                (uint32_t)(wm * 16 + ((q8 & 1) << 3) + r8) * 80 + ks * 32 + (q8 >> 1) * 16
                + cur * 5120;
            ldsm4(ah, uVh + aoff);
            ldsm4(al, uVl + aoff);
            uint32_t bhf[8][2], blf[8][2];
#pragma unroll
            for (int tp = 0; tp < 4; tp++) {
                const uint32_t boff =
                    (uint32_t)(ks * 16 + ((q8 & 1) << 3) + r8) * 272
                    + (wn * 64 + tp * 16) * 2 + (q8 >> 1) * 16;
                uint32_t tmp[4];
                ldsm4t(tmp, uEhc + boff);
                bhf[tp * 2][0] = tmp[0]; bhf[tp * 2][1] = tmp[1];
                bhf[tp * 2 + 1][0] = tmp[2]; bhf[tp * 2 + 1][1] = tmp[3];
                ldsm4t(tmp, uElc + boff);
                blf[tp * 2][0] = tmp[0]; blf[tp * 2][1] = tmp[1];
                blf[tp * 2 + 1][0] = tmp[2]; blf[tp * 2 + 1][1] = tmp[3];
            }
#pragma unroll
            for (int n = 0; n < 8; n++) {
                mma16816(c[n], ah, bhf[n]);
                mma16816(c[n], ah, blf[n]);
                mma16816(c[n], al, bhf[n]);
            }
        }

        // attn writeback chunk ci from E[cur]
        {
            const float iv = invs[ci * 32 + cs];
            const uint32_t sb2 = cur * 8704 + cs * 272 + cq * 32;
            const uint4 H0 = *(const uint4*)(sm + 69632 + sb2);
            const uint4 H1 = *(const uint4*)(sm + 69632 + sb2 + 16);
            const uint4 L0 = *(const uint4*)(sm + 87040 + sb2);
            const uint4 L1 = *(const uint4*)(sm + 87040 + sb2 + 16);
            const uint32_t hs[8] = {H0.x, H0.y, H0.z, H0.w, H1.x, H1.y, H1.z, H1.w};
            const uint32_t ls[8] = {L0.x, L0.y, L0.z, L0.w, L1.x, L1.y, L1.z, L1.w};
            float* op = &Ab[(size_t)(ci * 32 + cs) * S_DIM + t0 + cq * 16];
#pragma unroll
            for (int i = 0; i < 4; i++) {
                float4 a4;
                a4.x = (__uint_as_float(hs[2 * i] << 16)
                        + __uint_as_float(ls[2 * i] << 16)) * iv;
                a4.y = (__uint_as_float(hs[2 * i] & 0xFFFF0000u)
                        + __uint_as_float(ls[2 * i] & 0xFFFF0000u)) * iv;
                a4.z = (__uint_as_float(hs[2 * i + 1] << 16)
                        + __uint_as_float(ls[2 * i + 1] << 16)) * iv;
                a4.w = (__uint_as_float(hs[2 * i + 1] & 0xFFFF0000u)
                        + __uint_as_float(ls[2 * i + 1] & 0xFFFF0000u)) * iv;
                *(float4*)(op + i * 4) = a4;
            }
        }
        if (ci == 31) break;

        // d) barrier: E[nxt] visible; readers of cur buffers done
        __syncthreads();
        // e) prefetch V(ci+2) into V[cur]; wait older groups
        if (ci + 2 < 32) {
            CPV(ci + 2, cur);
            asm volatile("cp.async.wait_group %0;" :: "n"(1));
        } else {
            asm volatile("cp.async.wait_group %0;" :: "n"(0));
        }
        // f) barrier: cp data visible to all threads
        __syncthreads();
    }

    // ---- ctx epilogue ----
    __syncthreads();
#pragma unroll
    for (int n = 0; n < 8; n++) {
        const int tb = wn * 64 + n * 8 + l4 * 2;
        const int d0 = wm * 16 + g4;
        Cs[tb * 66 + d0]           = c[n][0];
        Cs[(tb + 1) * 66 + d0]     = c[n][1];
        Cs[tb * 66 + d0 + 8]       = c[n][2];
        Cs[(tb + 1) * 66 + d0 + 8] = c[n][3];
    }
    __syncthreads();
#pragma unroll
    for (int rr = 0; rr < 16; rr++) {
        const int t = w * 16 + rr;
        const float2 v = *(const float2*)&Cs[t * 66 + lane * 2];
        *(float2*)&ctx[((size_t)b * S_DIM + t0 + t) * (H_NUM * D_DIM)
                       + h * D_DIM + lane * 2] = v;
    }
}

// ---------------------------------------------------------------------------
extern "C" void kernel_launch(void* const* d_in, const int* in_sizes, int n_in,
                              void* d_out, int out_size)
{
    (void)in_sizes; (void)n_in; (void)out_size;
    const float* Q = (const float*)d_in[0];
    const float* K = (const float*)d_in[1];
    const float* V = (const float*)d_in[2];
    const int* mask = (const int*)d_in[3];

    float* ctx  = (float*)d_out;                 // (B, S, H*D)
    float* attn = ctx + CTX_ELEMS;               // (B, H, S, S)

    static int attr_set = 0;
    if (!attr_set) {
        cudaFuncSetAttribute(rows_kernel, cudaFuncAttributeMaxDynamicSharedMemorySize,
                             ROWS_DSMEM);
        cudaFuncSetAttribute(pv3_kernel, cudaFuncAttributeMaxDynamicSharedMemorySize,
                             PV3_DSMEM);
        attr_set = 1;
    }

    convert_kernel<<<dim3(16, NBH, 2), 256>>>(K, Q);
    rows_kernel<<<dim3(8, NBH), 256, ROWS_DSMEM>>>(mask);
    vsplit_kernel<<<dim3(4, NBH), 256>>>(V);
    pv3_kernel<<<dim3(8, NBH), 256, PV3_DSMEM>>>(mask, attn, ctx);
}

// round 15
// speedup vs baseline: 2.6671x; 1.2296x over previous
#include <cuda_runtime.h>
#include <cuda_bf16.h>
#include <cuda_fp16.h>
#include <cstdint>

// Shapes (fixed): B=8, H=12, D=64, S=1024
// scores[b,h,s,t] = (1/8) * sum_d K[b,h,d,s] * Q[b,h,d,t]
// mask over t (per b), softmax over t, context[b,h,d,t] = sum_s V[b,h,d,s]*attn[b,h,s,t]
// out = concat( context as (B,S,H*D), attn as (B,H,S,S) )
//
// convert_kernel : K,Q fp32 -> bf16 hi/lo planes [bh][s][d]. (unchanged)
// rows_kernel    : QK MMA (bf16 3-pass) row sums. (unchanged)
// vsplit_kernel  : inv = 1/rowsum; writes inv*V as FP16 hi/lo planes + g_inv.
// pv4_kernel     : pipelined. phase1: QK bf16 3-pass -> e fp32 regs ->
//                  attn STG directly (e*inv) + single-fp16 E STS.
//                  phase2: PV fp16 2-pass (Vh*E + Vl*E).

#define D_DIM 64
#define S_DIM 1024
#define H_NUM 12
#define B_NUM 8
#define NBH   (B_NUM * H_NUM)
#define CTX_ELEMS ((size_t)B_NUM * S_DIM * H_NUM * D_DIM)   // 6291456
#define PLANE_ELEMS (NBH * S_DIM * D_DIM)                    // 6291456

__device__ __forceinline__ unsigned s2u(const void* p) {
    return (unsigned)__cvta_generic_to_shared(p);
}
__device__ __forceinline__ uint32_t swz128(uint32_t off) {
    return off ^ ((off >> 3) & 0x70);
}
__device__ __forceinline__ void ldsm4(uint32_t* r, uint32_t addr) {
    asm volatile("ldmatrix.sync.aligned.m8n8.x4.shared.b16 {%0,%1,%2,%3}, [%4];"
                 : "=r"(r[0]), "=r"(r[1]), "=r"(r[2]), "=r"(r[3]) : "r"(addr));
}
__device__ __forceinline__ void ldsm4t(uint32_t* r, uint32_t addr) {
    asm volatile("ldmatrix.sync.aligned.m8n8.x4.trans.shared.b16 {%0,%1,%2,%3}, [%4];"
                 : "=r"(r[0]), "=r"(r[1]), "=r"(r[2]), "=r"(r[3]) : "r"(addr));
}
__device__ __forceinline__ void mma16816(float* c, const uint32_t* a, const uint32_t* b) {
    asm volatile(
        "mma.sync.aligned.m16n8k16.row.col.f32.bf16.bf16.f32 "
        "{%0,%1,%2,%3}, {%4,%5,%6,%7}, {%8,%9}, {%0,%1,%2,%3};"
        : "+f"(c[0]), "+f"(c[1]), "+f"(c[2]), "+f"(c[3])
        : "r"(a[0]), "r"(a[1]), "r"(a[2]), "r"(a[3]), "r"(b[0]), "r"(b[1]));
}
__device__ __forceinline__ void mma16816h(float* c, const uint32_t* a, const uint32_t* b) {
    asm volatile(
        "mma.sync.aligned.m16n8k16.row.col.f32.f16.f16.f32 "
        "{%0,%1,%2,%3}, {%4,%5,%6,%7}, {%8,%9}, {%0,%1,%2,%3};"
        : "+f"(c[0]), "+f"(c[1]), "+f"(c[2]), "+f"(c[3])
        : "r"(a[0]), "r"(a[1]), "r"(a[2]), "r"(a[3]), "r"(b[0]), "r"(b[1]));
}
// bf16x2 pack: low 16 = lo arg
__device__ __forceinline__ uint32_t cvt2(float lo, float hi) {
    uint32_t r;
    asm("cvt.rn.bf16x2.f32 %0, %1, %2;" : "=r"(r) : "f"(hi), "f"(lo));
    return r;
}
// fp16x2 pack: low 16 = lo arg
__device__ __forceinline__ uint32_t cvt2h(float lo, float hi) {
    uint32_t r;
    asm("cvt.rn.f16x2.f32 %0, %1, %2;" : "=r"(r) : "f"(hi), "f"(lo));
    return r;
}
#define CP16(dst_u, src_p) \
    asm volatile("cp.async.cg.shared.global [%0], [%1], 16;" :: "r"(dst_u), "l"(src_p))
#define CP_COMMIT() asm volatile("cp.async.commit_group;")

// ---------------- global scratch ----------------
__device__ __nv_bfloat16 g_cvt[4 * PLANE_ELEMS];     // 0=Khi 1=Klo 2=Qhi 3=Qlo [bh][s][d]
__device__ float g_part[8 * NBH * S_DIM];            // [slot(2)][bh][s]
__device__ __half g_Vh[PLANE_ELEMS];                 // inv*V fp16 hi [bh][d][s]
__device__ __half g_Vl[PLANE_ELEMS];                 // inv*V fp16 lo
__device__ float g_inv[NBH * S_DIM];

// ---------------------------------------------------------------------------
// convert_kernel (unchanged)
// ---------------------------------------------------------------------------
__global__ __launch_bounds__(256) void convert_kernel(
    const float* __restrict__ K, const float* __restrict__ Q)
{
    const int z = blockIdx.z;
    const int bh = blockIdx.y;
    const int s0 = blockIdx.x * 64;
    const float* X = z ? Q : K;
    __nv_bfloat16* hiP = g_cvt + (size_t)(z * 2) * PLANE_ELEMS;
    __nv_bfloat16* loP = g_cvt + (size_t)(z * 2 + 1) * PLANE_ELEMS;

    __shared__ float t[64][68];
    const int tid = threadIdx.x;

#pragma unroll
    for (int j = 0; j < 4; j++) {
        const int d = (tid >> 4) + j * 16;
        const int s = (tid & 15) * 4;
        const float4 v = *(const float4*)&X[(((size_t)bh * 64 + d) << 10) + s0 + s];
        t[d][s + 0] = v.x; t[d][s + 1] = v.y; t[d][s + 2] = v.z; t[d][s + 3] = v.w;
    }
    __syncthreads();

    const int sl = tid >> 2;
    const int dq = (tid & 3) * 16;
    __align__(16) __nv_bfloat16 hb[16], lb[16];
#pragma unroll
    for (int q = 0; q < 16; q++) {
        const float x = t[dq + q][sl];
        const __nv_bfloat16 h = __float2bfloat16_rn(x);
        hb[q] = h;
        lb[q] = __float2bfloat16_rn(x - __bfloat162float(h));
    }
    const size_t o = ((size_t)bh * S_DIM + s0 + sl) * D_DIM + dq;
    *(uint4*)&hiP[o]     = *(const uint4*)&hb[0];
    *(uint4*)&hiP[o + 8] = *(const uint4*)&hb[8];
    *(uint4*)&loP[o]     = *(const uint4*)&lb[0];
    *(uint4*)&loP[o + 8] = *(const uint4*)&lb[8];
}

// ---------------------------------------------------------------------------
// rows_kernel (unchanged)
// ---------------------------------------------------------------------------
#define ROWS_DSMEM (65536 + 512)

__global__ __launch_bounds__(256) void rows_kernel(const int* __restrict__ mask)
{
    extern __shared__ char sm[];
    const uint32_t sb = s2u(sm);
    float* fmask = (float*)(sm + 65536);

    const int bh = blockIdx.y;
    const int s0 = blockIdx.x * 128;
    const int b = bh / H_NUM;
    const int tid = threadIdx.x;
    const int w = tid >> 5, lane = tid & 31;
    const int wm = w & 3, wn = w >> 2;
    const int q8 = lane >> 3, r8 = lane & 7;
    const int g4 = lane >> 2, l4 = lane & 3;

#pragma unroll
    for (int u = 0; u < 8; u++) {
        const int id = tid + u * 256;
        const int T = id >> 10;
        const int r = (id >> 3) & 127;
        const int c = id & 7;
        const __nv_bfloat16* src = g_cvt + (size_t)T * PLANE_ELEMS
            + ((size_t)bh * S_DIM + s0 + r) * D_DIM + c * 8;
        CP16(sb + T * 16384 + swz128(r * 128 + c * 16), src);
    }
    CP_COMMIT();

    float acc[2][2] = {{0.f, 0.f}, {0.f, 0.f}};

    for (int tb = 0; tb < 8; tb++) {
#pragma unroll
        for (int u = 0; u < 8; u++) {
            const int id = tid + u * 256;
            const int T = id >> 10;
            const int r = (id >> 3) & 127;
            const int c = id & 7;
            const __nv_bfloat16* src = g_cvt + (size_t)(2 + T) * PLANE_ELEMS
                + ((size_t)bh * S_DIM + tb * 128 + r) * D_DIM + c * 8;
            CP16(sb + 32768 + T * 16384 + swz128(r * 128 + c * 16), src);
        }
        CP_COMMIT();
        if (tid < 128) fmask[tid] = mask[b * S_DIM + tb * 128 + tid] ? 1.0f : 0.0f;
        asm volatile("cp.async.wait_group 0;");
        __syncthreads();

        float c[2][8][4];
#pragma unroll
        for (int m = 0; m < 2; m++)
#pragma unroll
            for (int n = 0; n < 8; n++)
#pragma unroll
                for (int i = 0; i < 4; i++) c[m][n][i] = 0.f;

#pragma unroll
        for (int ks = 0; ks < 4; ks++) {
            uint32_t ah[2][4], al[2][4], bh2[8][2], bl2[8][2];
#pragma unroll
            for (int m = 0; m < 2; m++) {
                const int rowA = wm * 32 + m * 16 + ((q8 & 1) << 3) + r8;
                const uint32_t off = swz128(rowA * 128 + (2 * ks + (q8 >> 1)) * 16);
                ldsm4(ah[m], sb + off);
                ldsm4(al[m], sb + 16384 + off);
            }
#pragma unroll
            for (int np = 0; np < 4; np++) {
                const int rowB = wn * 64 + np * 16 + ((q8 >> 1) << 3) + r8;
                const uint32_t off = swz128(rowB * 128 + (2 * ks + (q8 & 1)) * 16);
                uint32_t tmp[4];
                ldsm4(tmp, sb + 32768 + off);
                bh2[np * 2][0] = tmp[0]; bh2[np * 2][1] = tmp[1];
                bh2[np * 2 + 1][0] = tmp[2]; bh2[np * 2 + 1][1] = tmp[3];
                ldsm4(tmp, sb + 49152 + off);
                bl2[np * 2][0] = tmp[0]; bl2[np * 2][1] = tmp[1];
                bl2[np * 2 + 1][0] = tmp[2]; bl2[np * 2 + 1][1] = tmp[3];
            }
#pragma unroll
            for (int m = 0; m < 2; m++)
#pragma unroll
                for (int n = 0; n < 8; n++) {
                    mma16816(c[m][n], ah[m], bh2[n]);
                    mma16816(c[m][n], ah[m], bl2[n]);
                    mma16816(c[m][n], al[m], bh2[n]);
                }
        }

#pragma unroll
        for (int m = 0; m < 2; m++)
#pragma unroll
            for (int n = 0; n < 8; n++) {
                const int cn = wn * 64 + n * 8 + l4 * 2;
                const float f0 = fmask[cn], f1 = fmask[cn + 1];
                acc[m][0] += __expf(c[m][n][0] * 0.125f) * f0
                           + __expf(c[m][n][1] * 0.125f) * f1;
                acc[m][1] += __expf(c[m][n][2] * 0.125f) * f0
                           + __expf(c[m][n][3] * 0.125f) * f1;
            }
        __syncthreads();
    }

#pragma unroll
    for (int m = 0; m < 2; m++)
#pragma unroll
        for (int p = 0; p < 2; p++) {
            float v = acc[m][p];
            v += __shfl_xor_sync(0xffffffffu, v, 1);
            v += __shfl_xor_sync(0xffffffffu, v, 2);
            acc[m][p] = v;
        }
    if (l4 == 0) {
        float* pp = &g_part[((wn * NBH + bh) << 10) + s0];
        pp[wm * 32 + g4]      = acc[0][0];
        pp[wm * 32 + g4 + 8]  = acc[0][1];
        pp[wm * 32 + g4 + 16] = acc[1][0];
        pp[wm * 32 + g4 + 24] = acc[1][1];
    }
}

// ---------------------------------------------------------------------------
// vsplit_kernel: inv = 1/(slot0+slot1); writes inv*V FP16 hi/lo planes + g_inv.
// ---------------------------------------------------------------------------
__global__ __launch_bounds__(256) void vsplit_kernel(const float* __restrict__ V)
{
    __shared__ float inv[256];
    const int bh = blockIdx.y;
    const int q = blockIdx.x;
    const int tid = threadIdx.x;
    {
        const float sum = g_part[((0 * NBH + bh) << 10) + q * 256 + tid]
                        + g_part[((1 * NBH + bh) << 10) + q * 256 + tid];
        const float iv = 1.0f / sum;
        inv[tid] = iv;
        g_inv[bh * S_DIM + q * 256 + tid] = iv;
    }
    __syncthreads();

    const float* Vb = V + (size_t)bh * D_DIM * S_DIM + q * 256;
    __half* Hh = g_Vh + (size_t)bh * D_DIM * S_DIM + q * 256;
    __half* Hl = g_Vl + (size_t)bh * D_DIM * S_DIM + q * 256;

#pragma unroll
    for (int u = 0; u < 16; u++) {
        const int f = tid + u * 256;
        const int dr = f >> 6;
        const int c4 = (f & 63) * 4;
        float4 v = *(const float4*)&Vb[(size_t)dr * S_DIM + c4];
        const float4 iv = *(const float4*)&inv[c4];
        v.x *= iv.x; v.y *= iv.y; v.z *= iv.z; v.w *= iv.w;
        const uint32_t h01 = cvt2h(v.x, v.y);
        const uint32_t h23 = cvt2h(v.z, v.w);
        const float hx = __half2float(__ushort_as_half((unsigned short)(h01 & 0xFFFF)));
        const float hy = __half2float(__ushort_as_half((unsigned short)(h01 >> 16)));
        const float hz = __half2float(__ushort_as_half((unsigned short)(h23 & 0xFFFF)));
        const float hw = __half2float(__ushort_as_half((unsigned short)(h23 >> 16)));
        const uint32_t l01 = cvt2h(v.x - hx, v.y - hy);
        const uint32_t l23 = cvt2h(v.z - hz, v.w - hw);
        *(uint2*)&Hh[(size_t)dr * S_DIM + c4] = make_uint2(h01, h23);
        *(uint2*)&Hl[(size_t)dr * S_DIM + c4] = make_uint2(l01, l23);
    }
}

// ---------------------------------------------------------------------------
// pv4_kernel: pipelined flash PV.
// phase1 (look-ahead): QK bf16 3-pass for chunk cc -> e fp32 regs ->
//   attn STG (e*inv) + single fp16 E STS (double-buffered).
// phase2: PV fp16 2-pass from E[cur], Vh/Vl[cur].
// smem: 0 Qhi 16384 | 16384 Qlo | 32768 Kh[2][4096] | 40960 Kl[2][4096]
//       | 49152 Vh[2][5120] | 59392 Vl[2][5120]
//       | 69632 E[2][8704] fp16 | 87040 invs[1024] f32  -> total 91136
// Cs[128][66] f32 aliases base.
// ---------------------------------------------------------------------------
#define PV4_DSMEM 91136

__global__ __launch_bounds__(256, 2) void pv4_kernel(
    const int* __restrict__ mask, float* __restrict__ attn, float* __restrict__ ctx)
{
    extern __shared__ char sm[];
    const uint32_t sb = s2u(sm);
    const uint32_t uKh = sb + 32768, uKl = sb + 40960;
    const uint32_t uVh = sb + 49152, uVl = sb + 59392;
    const uint32_t uE  = sb + 69632;
    float* invs = (float*)(sm + 87040);
    float* Cs = (float*)sm;

    const int bh = blockIdx.y;
    const int t0 = blockIdx.x * 128;
    const int b = bh / H_NUM;
    const int h = bh - b * H_NUM;
    const __nv_bfloat16* Khg = g_cvt + (size_t)bh * S_DIM * D_DIM;
    const __nv_bfloat16* Klg = g_cvt + PLANE_ELEMS + (size_t)bh * S_DIM * D_DIM;
    const __half* Vhg = g_Vh + (size_t)bh * D_DIM * S_DIM;
    const __half* Vlg = g_Vl + (size_t)bh * D_DIM * S_DIM;
    float* Ab = attn + (size_t)bh * S_DIM * S_DIM;

    const int tid = threadIdx.x;
    const int w = tid >> 5, lane = tid & 31;
    const int wm = w & 3, wn = w >> 2;
    const int q8 = lane >> 3, r8 = lane & 7;
    const int g4 = lane >> 2, l4 = lane & 3;
    const int kr = tid >> 3, kc = tid & 7;
    const int vrow = tid >> 2, vc = tid & 3;

    // per-thread epilogue mask (fixed columns)
    float fmr[2][2];
#pragma unroll
    for (int n = 0; n < 2; n++) {
        const int cn = w * 16 + n * 8 + l4 * 2;
        fmr[n][0] = mask[b * S_DIM + t0 + cn] ? 1.0f : 0.0f;
        fmr[n][1] = mask[b * S_DIM + t0 + cn + 1] ? 1.0f : 0.0f;
    }

    // stage Q tiles once (bf16 hi/lo)
#pragma unroll
    for (int u = 0; u < 8; u++) {
        const int id = tid + u * 256;
        const int T = id >> 10;
        const int r = (id >> 3) & 127;
        const int c = id & 7;
        const __nv_bfloat16* src = g_cvt + (size_t)(2 + T) * PLANE_ELEMS
            + ((size_t)bh * S_DIM + t0 + r) * D_DIM + c * 8;
        CP16(sb + T * 16384 + swz128(r * 128 + c * 16), src);
    }
    CP_COMMIT();

#define CPK(ci, buf)                                                           \
    {                                                                          \
        CP16(uKh + (buf) * 4096 + swz128(kr * 128 + kc * 16),                  \
             Khg + (size_t)((ci) * 32 + kr) * D_DIM + kc * 8);                 \
        CP16(uKl + (buf) * 4096 + swz128(kr * 128 + kc * 16),                  \
             Klg + (size_t)((ci) * 32 + kr) * D_DIM + kc * 8);                 \
        CP_COMMIT();                                                           \
    }
#define CPV(ci, buf)                                                           \
    {                                                                          \
        CP16(uVh + (buf) * 5120 + vrow * 80 + vc * 16,                         \
             Vhg + (size_t)vrow * S_DIM + (ci) * 32 + vc * 8);                 \
        CP16(uVl + (buf) * 5120 + vrow * 80 + vc * 16,                         \
             Vlg + (size_t)vrow * S_DIM + (ci) * 32 + vc * 8);                 \
        CP_COMMIT();                                                           \
    }

    CPK(0, 0); CPV(0, 0);
    CPK(1, 1); CPV(1, 1);

#pragma unroll
    for (int j = 0; j < 4; j++)
        invs[tid + j * 256] = g_inv[bh * S_DIM + tid + j * 256];

    asm volatile("cp.async.wait_group 0;");
    __syncthreads();

    // phase1: QK bf16 3-pass chunk cc using K buf kb -> attn STG + fp16 E -> buf eb
#define PHASE1(cc, kb, eb)                                                     \
    {                                                                          \
        float c2[2][2][4];                                                     \
        _Pragma("unroll")                                                      \
        for (int m = 0; m < 2; m++)                                            \
            _Pragma("unroll")                                                  \
            for (int n = 0; n < 2; n++)                                        \
                _Pragma("unroll")                                              \
                for (int i = 0; i < 4; i++) c2[m][n][i] = 0.f;                 \
        _Pragma("unroll")                                                      \
        for (int ks = 0; ks < 4; ks++) {                                       \
            uint32_t ah[2][4], al[2][4], bqh[2][2], bql[2][2];                 \
            _Pragma("unroll")                                                  \
            for (int m = 0; m < 2; m++) {                                      \
                const int rowA = m * 16 + ((q8 & 1) << 3) + r8;                \
                const uint32_t off = swz128(rowA * 128 + (2 * ks + (q8 >> 1)) * 16) \
                                   + (kb) * 4096;                              \
                ldsm4(ah[m], uKh + off);                                       \
                ldsm4(al[m], uKl + off);                                       \
            }                                                                  \
            {                                                                  \
                const int rowB = w * 16 + ((q8 >> 1) << 3) + r8;               \
                const uint32_t off = swz128(rowB * 128 + (2 * ks + (q8 & 1)) * 16); \
                uint32_t tmp[4];                                               \
                ldsm4(tmp, sb + off);                                          \
                bqh[0][0] = tmp[0]; bqh[0][1] = tmp[1];                        \
                bqh[1][0] = tmp[2]; bqh[1][1] = tmp[3];                        \
                ldsm4(tmp, sb + 16384 + off);                                  \
                bql[0][0] = tmp[0]; bql[0][1] = tmp[1];                        \
                bql[1][0] = tmp[2]; bql[1][1] = tmp[3];                        \
            }                                                                  \
            _Pragma("unroll")                                                  \
            for (int m = 0; m < 2; m++)                                        \
                _Pragma("unroll")                                              \
                for (int n = 0; n < 2; n++) {                                  \
                    mma16816(c2[m][n], ah[m], bqh[n]);                         \
                    mma16816(c2[m][n], ah[m], bql[n]);                         \
                    mma16816(c2[m][n], al[m], bqh[n]);                         \
                }                                                              \
        }                                                                      \
        _Pragma("unroll")                                                      \
        for (int m = 0; m < 2; m++)                                            \
            _Pragma("unroll")                                                  \
            for (int n = 0; n < 2; n++) {                                      \
                const int rm = m * 16 + g4;                                    \
                const int cn = w * 16 + n * 8 + l4 * 2;                        \
                const float e0 = __expf(c2[m][n][0] * 0.125f) * fmr[n][0];     \
                const float e1 = __expf(c2[m][n][1] * 0.125f) * fmr[n][1];     \
                const float e2 = __expf(c2[m][n][2] * 0.125f) * fmr[n][0];     \
                const float e3 = __expf(c2[m][n][3] * 0.125f) * fmr[n][1];     \
                const float iv0 = invs[(cc) * 32 + rm];                        \
                const float iv1 = invs[(cc) * 32 + rm + 8];                    \
                float2 a01; a01.x = e0 * iv0; a01.y = e1 * iv0;                \
                float2 a23; a23.x = e2 * iv1; a23.y = e3 * iv1;                \
                *(float2*)&Ab[(size_t)((cc) * 32 + rm) * S_DIM + t0 + cn] = a01; \
                *(float2*)&Ab[(size_t)((cc) * 32 + rm + 8) * S_DIM + t0 + cn] = a23; \
                *(uint32_t*)(sm + 69632 + (eb) * 8704 + rm * 272 + cn * 2)       \
                    = cvt2h(e0, e1);                                           \
                *(uint32_t*)(sm + 69632 + (eb) * 8704 + (rm + 8) * 272 + cn * 2) \
                    = cvt2h(e2, e3);                                           \
            }                                                                  \
    }

    // prologue: E(0) + attn(0)
    PHASE1(0, 0, 0);
    __syncthreads();

    float c[8][4];
#pragma unroll
    for (int n = 0; n < 8; n++)
#pragma unroll
        for (int i = 0; i < 4; i++) c[n][i] = 0.f;

    for (int ci = 0; ci < 32; ci++) {
        const int cur = ci & 1, nxt = cur ^ 1;

        // a) prefetch K(ci+2) into K[cur] (dead this iteration)
        if (ci + 2 < 32) CPK(ci + 2, cur);

        // b) phase1: E(ci+1) + attn(ci+1), look-ahead
        if (ci < 31) PHASE1(ci + 1, nxt, nxt);

        // c) phase2: PV fp16 2-pass on chunk ci
        const uint32_t uEc = uE + cur * 8704;
#pragma unroll
        for (int ks = 0; ks < 2; ks++) {
            uint32_t vh[4], vl[4];
            const uint32_t aoff =
                (uint32_t)(wm * 16 + ((q8 & 1) << 3) + r8) * 80 + ks * 32 + (q8 >> 1) * 16
                + cur * 5120;
            ldsm4(vh, uVh + aoff);
            ldsm4(vl, uVl + aoff);
            uint32_t ef[8][2];
#pragma unroll
            for (int tp = 0; tp < 4; tp++) {
                const uint32_t boff =
                    (uint32_t)(ks * 16 + ((q8 & 1) << 3) + r8) * 272
                    + (wn * 64 + tp * 16) * 2 + (q8 >> 1) * 16;
                uint32_t tmp[4];
                ldsm4t(tmp, uEc + boff);
                ef[tp * 2][0] = tmp[0]; ef[tp * 2][1] = tmp[1];
                ef[tp * 2 + 1][0] = tmp[2]; ef[tp * 2 + 1][1] = tmp[3];
            }
#pragma unroll
            for (int n = 0; n < 8; n++) {
                mma16816h(c[n], vh, ef[n]);
                mma16816h(c[n], vl, ef[n]);
            }
        }
        if (ci == 31) break;

        // d) barrier: E[nxt]/attn stores done; readers of cur buffers done
        __syncthreads();
        // e) prefetch V(ci+2) into V[cur]
        if (ci + 2 < 32) {
            CPV(ci + 2, cur);
            asm volatile("cp.async.wait_group %0;" :: "n"(1));
        } else {
            asm volatile("cp.async.wait_group %0;" :: "n"(0));
        }
        // f) barrier: cp data visible
        __syncthreads();
    }

    // ---- ctx epilogue ----
    __syncthreads();
#pragma unroll
    for (int n = 0; n < 8; n++) {
        const int tb = wn * 64 + n * 8 + l4 * 2;
        const int d0 = wm * 16 + g4;
        Cs[tb * 66 + d0]           = c[n][0];
        Cs[(tb + 1) * 66 + d0]     = c[n][1];
        Cs[tb * 66 + d0 + 8]       = c[n][2];
        Cs[(tb + 1) * 66 + d0 + 8] = c[n][3];
    }
    __syncthreads();
#pragma unroll
    for (int rr = 0; rr < 16; rr++) {
        const int t = w * 16 + rr;
        const float2 v = *(const float2*)&Cs[t * 66 + lane * 2];
        *(float2*)&ctx[((size_t)b * S_DIM + t0 + t) * (H_NUM * D_DIM)
                       + h * D_DIM + lane * 2] = v;
    }
}

// ---------------------------------------------------------------------------
extern "C" void kernel_launch(void* const* d_in, const int* in_sizes, int n_in,
                              void* d_out, int out_size)
{
    (void)in_sizes; (void)n_in; (void)out_size;
    const float* Q = (const float*)d_in[0];
    const float* K = (const float*)d_in[1];
    const float* V = (const float*)d_in[2];
    const int* mask = (const int*)d_in[3];

    float* ctx  = (float*)d_out;                 // (B, S, H*D)
    float* attn = ctx + CTX_ELEMS;               // (B, H, S, S)

    static int attr_set = 0;
    if (!attr_set) {
        cudaFuncSetAttribute(rows_kernel, cudaFuncAttributeMaxDynamicSharedMemorySize,
                             ROWS_DSMEM);
        cudaFuncSetAttribute(pv4_kernel, cudaFuncAttributeMaxDynamicSharedMemorySize,
                             PV4_DSMEM);
        attr_set = 1;
    }

    convert_kernel<<<dim3(16, NBH, 2), 256>>>(K, Q);
    rows_kernel<<<dim3(8, NBH), 256, ROWS_DSMEM>>>(mask);
    vsplit_kernel<<<dim3(4, NBH), 256>>>(V);
    pv4_kernel<<<dim3(8, NBH), 256, PV4_DSMEM>>>(mask, attn, ctx);
}